// round 7
// baseline (speedup 1.0000x reference)
#include <cuda_runtime.h>
#include <cuda_bf16.h>
#include <cuda_fp16.h>
#include <math.h>

// Problem dims (fixed by reference setup_inputs)
#define BB 4
#define TE 512
#define TD 256
#define DM 256
#define TT 4   // t-rows per CTA in score kernel

// Scratch: tanh of projections, f32 (allocation-free __device__ globals).
__device__ __align__(16) float g_Tw[BB * TE * DM];   // tanh(enc @ W_a)
__device__ __align__(16) float g_Tu[BB * TD * DM];   // tanh(dec @ U_a)

// ---------------------------------------------------------------------------
// Combined projection GEMM (enc@W_a and dec@U_a in one launch).
// Epilogue applies accurate tanhf and stores f32.
// Rows 0..2047 -> g_Tw, rows 2048..3071 -> g_Tu.
// BM=64, BN=64, BK=16, 256 threads, 4x4/thread, double-buffered SMEM.
// ---------------------------------------------------------------------------
__global__ void __launch_bounds__(256)
proj_gemm2(const float* __restrict__ enc, const float* __restrict__ dec,
           const float* __restrict__ Wa,  const float* __restrict__ Ua) {
    __shared__ float sA[2][16][64];   // sA[p][k][m]
    __shared__ float sB[2][16][64];   // sB[p][k][n]

    const int tid = threadIdx.x;
    const int tx = tid & 15;          // n-sub
    const int ty = tid >> 4;          // m-sub
    const int row0 = blockIdx.x * 64;
    const int n0   = blockIdx.y * 64;

    const float* X;
    const float* W;
    float* Y;
    if (row0 < BB * TE) {
        X = enc + (size_t)row0 * DM;  W = Wa;  Y = g_Tw + (size_t)row0 * DM;
    } else {
        const int r = row0 - BB * TE;
        X = dec + (size_t)r * DM;     W = Ua;  Y = g_Tu + (size_t)r * DM;
    }

    float acc[4][4];
#pragma unroll
    for (int i = 0; i < 4; i++)
#pragma unroll
        for (int j = 0; j < 4; j++) acc[i][j] = 0.f;

    const int lm  = tid >> 2;         // 0..63
    const int lkq = tid & 3;          // 0..3
    const int lr  = tid >> 4;         // 0..15
    const int lc  = tid & 15;         // 0..15

    // prologue: tile 0
    float4 av = *(const float4*)(X + lm * DM + 4 * lkq);
    float4 bv = *(const float4*)(W + lr * DM + n0 + 4 * lc);
    sA[0][4 * lkq + 0][lm] = av.x;
    sA[0][4 * lkq + 1][lm] = av.y;
    sA[0][4 * lkq + 2][lm] = av.z;
    sA[0][4 * lkq + 3][lm] = av.w;
    *(float4*)(&sB[0][lr][4 * lc]) = bv;
    __syncthreads();

    int p = 0;
#pragma unroll 1
    for (int kt = 0; kt < 16; kt++) {
        float4 av2, bv2;
        if (kt < 15) {
            av2 = *(const float4*)(X + lm * DM + (kt + 1) * 16 + 4 * lkq);
            bv2 = *(const float4*)(W + ((kt + 1) * 16 + lr) * DM + n0 + 4 * lc);
        }
#pragma unroll
        for (int kk = 0; kk < 16; kk++) {
            float4 a = *(const float4*)(&sA[p][kk][ty * 4]);
            float4 b = *(const float4*)(&sB[p][kk][tx * 4]);
            acc[0][0] += a.x * b.x; acc[0][1] += a.x * b.y; acc[0][2] += a.x * b.z; acc[0][3] += a.x * b.w;
            acc[1][0] += a.y * b.x; acc[1][1] += a.y * b.y; acc[1][2] += a.y * b.z; acc[1][3] += a.y * b.w;
            acc[2][0] += a.z * b.x; acc[2][1] += a.z * b.y; acc[2][2] += a.z * b.z; acc[2][3] += a.z * b.w;
            acc[3][0] += a.w * b.x; acc[3][1] += a.w * b.y; acc[3][2] += a.w * b.z; acc[3][3] += a.w * b.w;
        }
        if (kt < 15) {
            sA[p ^ 1][4 * lkq + 0][lm] = av2.x;
            sA[p ^ 1][4 * lkq + 1][lm] = av2.y;
            sA[p ^ 1][4 * lkq + 2][lm] = av2.z;
            sA[p ^ 1][4 * lkq + 3][lm] = av2.w;
            *(float4*)(&sB[p ^ 1][lr][4 * lc]) = bv2;
        }
        __syncthreads();
        p ^= 1;
    }

    // Epilogue: accurate tanh, store f32
#pragma unroll
    for (int i = 0; i < 4; i++) {
        float4 o = make_float4(tanhf(acc[i][0]), tanhf(acc[i][1]),
                               tanhf(acc[i][2]), tanhf(acc[i][3]));
        *(float4*)(Y + (ty * 4 + i) * DM + n0 + tx * 4) = o;
    }
}

// ---------------------------------------------------------------------------
// Score kernel: score via tanh-addition identity -> softmax -> attn weights.
// Grid: B * (TD/TT) = 256 CTAs, 512 threads, 2 CTAs/SM.
// Phase B: warp w -> e-block [w*32, w*32+32), ALL 4 t's per tw-load.
// Lane: e_idx = lane>>4 (2 e-rows/iter), d_sub = lane&15 (16 d's each).
// Per element: num=tw+tu; den=fma(tw,tu,1); contrib=v*num*rcp(den).
// ---------------------------------------------------------------------------
__global__ void __launch_bounds__(512, 2)
attn_score(const float* __restrict__ Va, float* __restrict__ out_attn) {
    __shared__ __align__(16) float s_tu[TT * DM];          // 4 KB
    __shared__ __align__(16) float s_v[DM];                // 1 KB
    __shared__ __align__(16) float s_score[TE][TT];        // 8 KB, e-major

    const int b    = blockIdx.x >> 6;
    const int t0   = (blockIdx.x & 63) * TT;
    const int tid  = threadIdx.x;
    const int warp = tid >> 5;
    const int lane = tid & 31;

    // ---- Phase A: stage Tu rows + V ----
    if (tid < 256) {
        ((float4*)s_tu)[tid] = ((const float4*)(g_Tu + (size_t)(b * TD + t0) * DM))[tid];
    } else if (tid < 320) {
        ((float4*)s_v)[tid - 256] = ((const float4*)Va)[tid - 256];
    }
    __syncthreads();

    // ---- Phase B: scores ----
    {
        const int e_idx = lane >> 4;      // 0..1
        const int d_sub = lane & 15;      // 0..15, owns 16 d's
        const int eb    = warp * 32;      // e-block

        // hoist v (16 f32)
        float v[16];
        {
            const float4* vp = (const float4*)(s_v + d_sub * 16);
            *(float4*)(&v[0])  = vp[0];
            *(float4*)(&v[4])  = vp[1];
            *(float4*)(&v[8])  = vp[2];
            *(float4*)(&v[12]) = vp[3];
        }

        const float4* wp = (const float4*)(g_Tw
                           + ((size_t)(b * TE) + eb + e_idx) * DM + d_sub * 16);

#pragma unroll 1
        for (int it = 0; it < 16; it++) {
            const int e = eb + 2 * it + e_idx;
            float tw[16];
            *(float4*)(&tw[0])  = wp[0];
            *(float4*)(&tw[4])  = wp[1];
            *(float4*)(&tw[8])  = wp[2];
            *(float4*)(&tw[12]) = wp[3];
            wp += 2 * (DM / 4);           // advance 2 e-rows

            float s4[4];
#pragma unroll
            for (int t = 0; t < 4; t++) {
                const float4* tup = (const float4*)(s_tu + t * DM + d_sub * 16);
                float acc0 = 0.f, acc1 = 0.f;
                // chunk 0: d 0..7
                {
                    float tu[8];
                    *(float4*)(&tu[0]) = tup[0];
                    *(float4*)(&tu[4]) = tup[1];
#pragma unroll
                    for (int j = 0; j < 8; j += 2) {
                        float n0 = tw[j]     + tu[j];
                        float d0 = fmaf(tw[j],     tu[j],     1.f);
                        float n1 = tw[j + 1] + tu[j + 1];
                        float d1 = fmaf(tw[j + 1], tu[j + 1], 1.f);
                        acc0 = fmaf(v[j],     __fdividef(n0, d0), acc0);
                        acc1 = fmaf(v[j + 1], __fdividef(n1, d1), acc1);
                    }
                }
                // chunk 1: d 8..15
                {
                    float tu[8];
                    *(float4*)(&tu[0]) = tup[2];
                    *(float4*)(&tu[4]) = tup[3];
#pragma unroll
                    for (int j = 0; j < 8; j += 2) {
                        float n0 = tw[j + 8] + tu[j];
                        float d0 = fmaf(tw[j + 8], tu[j],     1.f);
                        float n1 = tw[j + 9] + tu[j + 1];
                        float d1 = fmaf(tw[j + 9], tu[j + 1], 1.f);
                        acc0 = fmaf(v[j + 8], __fdividef(n0, d0), acc0);
                        acc1 = fmaf(v[j + 9], __fdividef(n1, d1), acc1);
                    }
                }
                s4[t] = acc0 + acc1;
            }
            // butterfly over the 16 d_sub lanes (stays within e_idx half)
#pragma unroll
            for (int off = 8; off > 0; off >>= 1) {
                s4[0] += __shfl_xor_sync(0xffffffffu, s4[0], off);
                s4[1] += __shfl_xor_sync(0xffffffffu, s4[1], off);
                s4[2] += __shfl_xor_sync(0xffffffffu, s4[2], off);
                s4[3] += __shfl_xor_sync(0xffffffffu, s4[3], off);
            }
            if (d_sub == 0)
                *(float4*)(&s_score[e][0]) = make_float4(s4[0], s4[1], s4[2], s4[3]);
        }
    }
    __syncthreads();

    // ---- Phase C: softmax over e (warps 0..3, one t each), write attn ----
    if (warp < TT) {
        const int t = warp;
        float vals[16];
        float mx = -1e30f;
#pragma unroll
        for (int k = 0; k < 16; k++) {
            vals[k] = s_score[lane + 32 * k][t];
            mx = fmaxf(mx, vals[k]);
        }
#pragma unroll
        for (int off = 16; off > 0; off >>= 1)
            mx = fmaxf(mx, __shfl_xor_sync(0xffffffffu, mx, off));
        float sum = 0.f;
#pragma unroll
        for (int k = 0; k < 16; k++) {
            vals[k] = exp2f((vals[k] - mx) * 1.4426950408889634f);
            sum += vals[k];
        }
#pragma unroll
        for (int off = 16; off > 0; off >>= 1)
            sum += __shfl_xor_sync(0xffffffffu, sum, off);
        const float inv = 1.0f / sum;
        float* arow = out_attn + ((size_t)(b * TD + t0 + t)) * TE;
#pragma unroll
        for (int k = 0; k < 16; k++)
            arow[lane + 32 * k] = vals[k] * inv;
    }
}

// ---------------------------------------------------------------------------
// Context GEMM: ctx[b,t,d] = sum_e attn[b,t,e] * enc[b,e,d].
// BM=32 (t), BN=64 (d), BK=32 (e). 256 threads, thread = 2m x 4n.
// Grid (8, 4, 4) = (t-tiles, d-tiles, b). attn tile stored transposed [e][t].
// ---------------------------------------------------------------------------
__global__ void __launch_bounds__(256)
attn_ctx(const float* __restrict__ enc, const float* __restrict__ attn,
         float* __restrict__ out_ctx) {
    __shared__ float sAttT[32][32];   // [e][t] (transposed on store)
    __shared__ float sEnc[32][64];    // [e][d]

    const int b  = blockIdx.z;
    const int t0 = blockIdx.x * 32;
    const int d0 = blockIdx.y * 64;
    const int tid = threadIdx.x;
    const int tx = tid & 15;          // n-sub (4 d's)
    const int ty = tid >> 4;          // m-sub (2 t's)

    const float* attb = attn + ((size_t)(b * TD + t0)) * TE;
    const float* encb = enc + (size_t)b * TE * DM;

    float acc[2][4];
#pragma unroll
    for (int i = 0; i < 2; i++)
#pragma unroll
        for (int j = 0; j < 4; j++) acc[i][j] = 0.f;

    const int am = tid >> 3;          // 0..31 t-row for attn load
    const int ak = (tid & 7) * 4;     // e-chunk
    const int er = tid >> 4;          // 0..15 e-row for enc load
    const int ec = (tid & 15) * 4;    // d-chunk

#pragma unroll 1
    for (int k0 = 0; k0 < TE; k0 += 32) {
        float4 a = *(const float4*)(attb + (size_t)am * TE + k0 + ak);
        float4 e0 = *(const float4*)(encb + (size_t)(k0 + er) * DM + d0 + ec);
        float4 e1 = *(const float4*)(encb + (size_t)(k0 + 16 + er) * DM + d0 + ec);
        // transpose attn into sAttT[e][t]
        sAttT[ak + 0][am] = a.x;
        sAttT[ak + 1][am] = a.y;
        sAttT[ak + 2][am] = a.z;
        sAttT[ak + 3][am] = a.w;
        *(float4*)(&sEnc[er][ec])      = e0;
        *(float4*)(&sEnc[16 + er][ec]) = e1;
        __syncthreads();

#pragma unroll
        for (int k = 0; k < 32; k++) {
            float2 av2 = *(const float2*)(&sAttT[k][ty * 2]);
            float4 bv = *(const float4*)(&sEnc[k][tx * 4]);
            acc[0][0] = fmaf(av2.x, bv.x, acc[0][0]);
            acc[0][1] = fmaf(av2.x, bv.y, acc[0][1]);
            acc[0][2] = fmaf(av2.x, bv.z, acc[0][2]);
            acc[0][3] = fmaf(av2.x, bv.w, acc[0][3]);
            acc[1][0] = fmaf(av2.y, bv.x, acc[1][0]);
            acc[1][1] = fmaf(av2.y, bv.y, acc[1][1]);
            acc[1][2] = fmaf(av2.y, bv.z, acc[1][2]);
            acc[1][3] = fmaf(av2.y, bv.w, acc[1][3]);
        }
        __syncthreads();
    }

#pragma unroll
    for (int i = 0; i < 2; i++) {
        float4 o = make_float4(acc[i][0], acc[i][1], acc[i][2], acc[i][3]);
        *(float4*)(out_ctx + ((size_t)(b * TD + t0 + ty * 2 + i)) * DM + d0 + tx * 4) = o;
    }
}

extern "C" void kernel_launch(void* const* d_in, const int* in_sizes, int n_in,
                              void* d_out, int out_size) {
    const float* enc = (const float*)d_in[0];   // [4,512,256]
    const float* dec = (const float*)d_in[1];   // [4,256,256]
    const float* Wa  = (const float*)d_in[2];   // [256,256]
    const float* Ua  = (const float*)d_in[3];   // [256,256]
    const float* Va  = (const float*)d_in[4];   // [256,1]

    float* out      = (float*)d_out;
    float* out_ctx  = out;                          // [4,256,256]
    float* out_attn = out + (size_t)BB * TD * DM;   // [4,256,512]

    // Projections + tanh epilogue: 192 CTAs
    proj_gemm2<<<dim3((BB * TE + BB * TD) / 64, DM / 64), 256>>>(enc, dec, Wa, Ua);

    // Scores + softmax: 256 CTAs
    attn_score<<<BB * (TD / TT), 512>>>(Va, out_attn);

    // Context GEMM: 128 CTAs
    attn_ctx<<<dim3(TD / 32, DM / 64, BB), 256>>>(enc, out_attn, out_ctx);
}

// round 8
// speedup vs baseline: 1.1488x; 1.1488x over previous
#include <cuda_runtime.h>
#include <cuda_bf16.h>
#include <cuda_fp16.h>
#include <math.h>

// Problem dims (fixed by reference setup_inputs)
#define BB 4
#define TE 512
#define TD 256
#define DM 256
#define TT 4   // t-rows per CTA in score kernel

// Scratch: tanh of projections, f32. +DM pad for prefetch overread.
__device__ __align__(16) float g_Tw[BB * TE * DM + DM];   // tanh(enc @ W_a)
__device__ __align__(16) float g_Tu[BB * TD * DM];        // tanh(dec @ U_a)

// Fast accurate-enough tanh: 1 - 2/(exp(2x)+1). ~1e-7 rel err.
__device__ __forceinline__ float fast_tanhf(float x) {
    float ex = __expf(2.0f * x);
    return 1.0f - __fdividef(2.0f, ex + 1.0f);
}

// ---------------------------------------------------------------------------
// Combined projection GEMM (enc@W_a and dec@U_a in one launch).
// Epilogue applies fast tanh, stores f32.
// Rows 0..2047 -> g_Tw, rows 2048..3071 -> g_Tu.
// BM=64, BN=64, BK=16, 256 threads, 4x4/thread, double-buffered SMEM.
// ---------------------------------------------------------------------------
__global__ void __launch_bounds__(256)
proj_gemm2(const float* __restrict__ enc, const float* __restrict__ dec,
           const float* __restrict__ Wa,  const float* __restrict__ Ua) {
    __shared__ float sA[2][16][64];   // sA[p][k][m]
    __shared__ float sB[2][16][64];   // sB[p][k][n]

    const int tid = threadIdx.x;
    const int tx = tid & 15;          // n-sub
    const int ty = tid >> 4;          // m-sub
    const int row0 = blockIdx.x * 64;
    const int n0   = blockIdx.y * 64;

    const float* X;
    const float* W;
    float* Y;
    if (row0 < BB * TE) {
        X = enc + (size_t)row0 * DM;  W = Wa;  Y = g_Tw + (size_t)row0 * DM;
    } else {
        const int r = row0 - BB * TE;
        X = dec + (size_t)r * DM;     W = Ua;  Y = g_Tu + (size_t)r * DM;
    }

    float acc[4][4];
#pragma unroll
    for (int i = 0; i < 4; i++)
#pragma unroll
        for (int j = 0; j < 4; j++) acc[i][j] = 0.f;

    const int lm  = tid >> 2;         // 0..63
    const int lkq = tid & 3;          // 0..3
    const int lr  = tid >> 4;         // 0..15
    const int lc  = tid & 15;         // 0..15

    // prologue: tile 0
    float4 av = *(const float4*)(X + lm * DM + 4 * lkq);
    float4 bv = *(const float4*)(W + lr * DM + n0 + 4 * lc);
    sA[0][4 * lkq + 0][lm] = av.x;
    sA[0][4 * lkq + 1][lm] = av.y;
    sA[0][4 * lkq + 2][lm] = av.z;
    sA[0][4 * lkq + 3][lm] = av.w;
    *(float4*)(&sB[0][lr][4 * lc]) = bv;
    __syncthreads();

    int p = 0;
#pragma unroll 1
    for (int kt = 0; kt < 16; kt++) {
        float4 av2, bv2;
        if (kt < 15) {
            av2 = *(const float4*)(X + lm * DM + (kt + 1) * 16 + 4 * lkq);
            bv2 = *(const float4*)(W + ((kt + 1) * 16 + lr) * DM + n0 + 4 * lc);
        }
#pragma unroll
        for (int kk = 0; kk < 16; kk++) {
            float4 a = *(const float4*)(&sA[p][kk][ty * 4]);
            float4 b = *(const float4*)(&sB[p][kk][tx * 4]);
            acc[0][0] += a.x * b.x; acc[0][1] += a.x * b.y; acc[0][2] += a.x * b.z; acc[0][3] += a.x * b.w;
            acc[1][0] += a.y * b.x; acc[1][1] += a.y * b.y; acc[1][2] += a.y * b.z; acc[1][3] += a.y * b.w;
            acc[2][0] += a.z * b.x; acc[2][1] += a.z * b.y; acc[2][2] += a.z * b.z; acc[2][3] += a.z * b.w;
            acc[3][0] += a.w * b.x; acc[3][1] += a.w * b.y; acc[3][2] += a.w * b.z; acc[3][3] += a.w * b.w;
        }
        if (kt < 15) {
            sA[p ^ 1][4 * lkq + 0][lm] = av2.x;
            sA[p ^ 1][4 * lkq + 1][lm] = av2.y;
            sA[p ^ 1][4 * lkq + 2][lm] = av2.z;
            sA[p ^ 1][4 * lkq + 3][lm] = av2.w;
            *(float4*)(&sB[p ^ 1][lr][4 * lc]) = bv2;
        }
        __syncthreads();
        p ^= 1;
    }

    // Epilogue: fast tanh, store f32
#pragma unroll
    for (int i = 0; i < 4; i++) {
        float4 o = make_float4(fast_tanhf(acc[i][0]), fast_tanhf(acc[i][1]),
                               fast_tanhf(acc[i][2]), fast_tanhf(acc[i][3]));
        *(float4*)(Y + (ty * 4 + i) * DM + n0 + tx * 4) = o;
    }
}

// ---------------------------------------------------------------------------
// Score kernel: tanh-addition identity -> softmax -> attn weights.
// Grid: B * (TD/TT) = 256 CTAs, 512 threads.
// Warp w -> e-block [w*32, (w+1)*32), all 4 t's per tw-load (4x reuse).
// Lane owns 8 d's (32 lanes cover DM=256). One e-row per iteration.
// tu[4][8], v[8], double-buffered tw[8] all in registers -> no LDS in loop.
// Per element: n=tw+tu; den=fma(tw,tu,1); q=n*rcp(den); acc=fma(v,q,acc).
// ---------------------------------------------------------------------------
__global__ void __launch_bounds__(512)
attn_score(const float* __restrict__ Va, float* __restrict__ out_attn) {
    __shared__ __align__(16) float s_tu[TT * DM];          // 4 KB
    __shared__ __align__(16) float s_v[DM];                // 1 KB
    __shared__ __align__(16) float s_score[TE][TT];        // 8 KB, e-major

    const int b    = blockIdx.x >> 6;
    const int t0   = (blockIdx.x & 63) * TT;
    const int tid  = threadIdx.x;
    const int warp = tid >> 5;
    const int lane = tid & 31;

    // ---- Phase A: stage Tu rows + V ----
    if (tid < 256) {
        ((float4*)s_tu)[tid] = ((const float4*)(g_Tu + (size_t)(b * TD + t0) * DM))[tid];
    } else if (tid < 320) {
        ((float4*)s_v)[tid - 256] = ((const float4*)Va)[tid - 256];
    }
    __syncthreads();

    // ---- Phase B: scores ----
    {
        const int dl = lane * 8;          // d-base for this lane
        const int eb = warp * 32;         // e-block

        // hoist tu for all 4 t's (32 regs) and v (8 regs)
        float tu[4][8];
#pragma unroll
        for (int t = 0; t < 4; t++) {
            const float4* up = (const float4*)(s_tu + t * DM + dl);
            *(float4*)(&tu[t][0]) = up[0];
            *(float4*)(&tu[t][4]) = up[1];
        }
        float v[8];
        {
            const float4* vp = (const float4*)(s_v + dl);
            *(float4*)(&v[0]) = vp[0];
            *(float4*)(&v[4]) = vp[1];
        }

        const float* wrow = g_Tw + ((size_t)(b * TE) + eb) * DM + dl;
        float cur[8];
        *(float4*)(&cur[0]) = *(const float4*)(wrow);
        *(float4*)(&cur[4]) = *(const float4*)(wrow + 4);

#pragma unroll 1
        for (int it = 0; it < 32; it++) {
            // prefetch next row (pad overread on final iter; values unused)
            wrow += DM;
            float nxt[8];
            *(float4*)(&nxt[0]) = *(const float4*)(wrow);
            *(float4*)(&nxt[4]) = *(const float4*)(wrow + 4);

            float s4[4];
#pragma unroll
            for (int t = 0; t < 4; t++) {
                float acc0 = 0.f, acc1 = 0.f;
#pragma unroll
                for (int j = 0; j < 8; j += 2) {
                    float n0 = cur[j]     + tu[t][j];
                    float d0 = fmaf(cur[j],     tu[t][j],     1.f);
                    float n1 = cur[j + 1] + tu[t][j + 1];
                    float d1 = fmaf(cur[j + 1], tu[t][j + 1], 1.f);
                    acc0 = fmaf(v[j],     __fdividef(n0, d0), acc0);
                    acc1 = fmaf(v[j + 1], __fdividef(n1, d1), acc1);
                }
                s4[t] = acc0 + acc1;
            }
            // full-warp butterfly: 5 stages x 4 scores
#pragma unroll
            for (int off = 16; off > 0; off >>= 1) {
                s4[0] += __shfl_xor_sync(0xffffffffu, s4[0], off);
                s4[1] += __shfl_xor_sync(0xffffffffu, s4[1], off);
                s4[2] += __shfl_xor_sync(0xffffffffu, s4[2], off);
                s4[3] += __shfl_xor_sync(0xffffffffu, s4[3], off);
            }
            if (lane == 0)
                *(float4*)(&s_score[eb + it][0]) = make_float4(s4[0], s4[1], s4[2], s4[3]);

#pragma unroll
            for (int j = 0; j < 8; j++) cur[j] = nxt[j];
        }
    }
    __syncthreads();

    // ---- Phase C: softmax over e (warps 0..3, one t each), write attn ----
    if (warp < TT) {
        const int t = warp;
        float vals[16];
        float mx = -1e30f;
#pragma unroll
        for (int k = 0; k < 16; k++) {
            vals[k] = s_score[lane + 32 * k][t];
            mx = fmaxf(mx, vals[k]);
        }
#pragma unroll
        for (int off = 16; off > 0; off >>= 1)
            mx = fmaxf(mx, __shfl_xor_sync(0xffffffffu, mx, off));
        float sum = 0.f;
#pragma unroll
        for (int k = 0; k < 16; k++) {
            vals[k] = exp2f((vals[k] - mx) * 1.4426950408889634f);
            sum += vals[k];
        }
#pragma unroll
        for (int off = 16; off > 0; off >>= 1)
            sum += __shfl_xor_sync(0xffffffffu, sum, off);
        const float inv = 1.0f / sum;
        float* arow = out_attn + ((size_t)(b * TD + t0 + t)) * TE;
#pragma unroll
        for (int k = 0; k < 16; k++)
            arow[lane + 32 * k] = vals[k] * inv;
    }
}

// ---------------------------------------------------------------------------
// Context GEMM: ctx[b,t,d] = sum_e attn[b,t,e] * enc[b,e,d].
// BM=32 (t), BN=64 (d), BK=32 (e). 256 threads, thread = 2m x 4n.
// Grid (8, 4, 4) = (t-tiles, d-tiles, b). attn tile stored transposed [e][t].
// ---------------------------------------------------------------------------
__global__ void __launch_bounds__(256)
attn_ctx(const float* __restrict__ enc, const float* __restrict__ attn,
         float* __restrict__ out_ctx) {
    __shared__ float sAttT[32][32];   // [e][t] (transposed on store)
    __shared__ float sEnc[32][64];    // [e][d]

    const int b  = blockIdx.z;
    const int t0 = blockIdx.x * 32;
    const int d0 = blockIdx.y * 64;
    const int tid = threadIdx.x;
    const int tx = tid & 15;          // n-sub (4 d's)
    const int ty = tid >> 4;          // m-sub (2 t's)

    const float* attb = attn + ((size_t)(b * TD + t0)) * TE;
    const float* encb = enc + (size_t)b * TE * DM;

    float acc[2][4];
#pragma unroll
    for (int i = 0; i < 2; i++)
#pragma unroll
        for (int j = 0; j < 4; j++) acc[i][j] = 0.f;

    const int am = tid >> 3;          // 0..31 t-row for attn load
    const int ak = (tid & 7) * 4;     // e-chunk
    const int er = tid >> 4;          // 0..15 e-row for enc load
    const int ec = (tid & 15) * 4;    // d-chunk

#pragma unroll 1
    for (int k0 = 0; k0 < TE; k0 += 32) {
        float4 a = *(const float4*)(attb + (size_t)am * TE + k0 + ak);
        float4 e0 = *(const float4*)(encb + (size_t)(k0 + er) * DM + d0 + ec);
        float4 e1 = *(const float4*)(encb + (size_t)(k0 + 16 + er) * DM + d0 + ec);
        // transpose attn into sAttT[e][t]
        sAttT[ak + 0][am] = a.x;
        sAttT[ak + 1][am] = a.y;
        sAttT[ak + 2][am] = a.z;
        sAttT[ak + 3][am] = a.w;
        *(float4*)(&sEnc[er][ec])      = e0;
        *(float4*)(&sEnc[16 + er][ec]) = e1;
        __syncthreads();

#pragma unroll
        for (int k = 0; k < 32; k++) {
            float2 av2 = *(const float2*)(&sAttT[k][ty * 2]);
            float4 bv = *(const float4*)(&sEnc[k][tx * 4]);
            acc[0][0] = fmaf(av2.x, bv.x, acc[0][0]);
            acc[0][1] = fmaf(av2.x, bv.y, acc[0][1]);
            acc[0][2] = fmaf(av2.x, bv.z, acc[0][2]);
            acc[0][3] = fmaf(av2.x, bv.w, acc[0][3]);
            acc[1][0] = fmaf(av2.y, bv.x, acc[1][0]);
            acc[1][1] = fmaf(av2.y, bv.y, acc[1][1]);
            acc[1][2] = fmaf(av2.y, bv.z, acc[1][2]);
            acc[1][3] = fmaf(av2.y, bv.w, acc[1][3]);
        }
        __syncthreads();
    }

#pragma unroll
    for (int i = 0; i < 2; i++) {
        float4 o = make_float4(acc[i][0], acc[i][1], acc[i][2], acc[i][3]);
        *(float4*)(out_ctx + ((size_t)(b * TD + t0 + ty * 2 + i)) * DM + d0 + tx * 4) = o;
    }
}

extern "C" void kernel_launch(void* const* d_in, const int* in_sizes, int n_in,
                              void* d_out, int out_size) {
    const float* enc = (const float*)d_in[0];   // [4,512,256]
    const float* dec = (const float*)d_in[1];   // [4,256,256]
    const float* Wa  = (const float*)d_in[2];   // [256,256]
    const float* Ua  = (const float*)d_in[3];   // [256,256]
    const float* Va  = (const float*)d_in[4];   // [256,1]

    float* out      = (float*)d_out;
    float* out_ctx  = out;                          // [4,256,256]
    float* out_attn = out + (size_t)BB * TD * DM;   // [4,256,512]

    // Projections + fast-tanh epilogue: 192 CTAs
    proj_gemm2<<<dim3((BB * TE + BB * TD) / 64, DM / 64), 256>>>(enc, dec, Wa, Ua);

    // Scores + softmax: 256 CTAs
    attn_score<<<BB * (TD / TT), 512>>>(Va, out_attn);

    // Context GEMM: 128 CTAs
    attn_ctx<<<dim3(TD / 32, DM / 64, BB), 256>>>(enc, out_attn, out_ctx);
}

// round 9
// speedup vs baseline: 1.1953x; 1.0405x over previous
#include <cuda_runtime.h>
#include <cuda_bf16.h>
#include <cuda_fp16.h>
#include <math.h>

// Problem dims (fixed by reference setup_inputs)
#define BB 4
#define TE 512
#define TD 256
#define DM 256
#define TT 4   // t-rows per CTA in score kernel

// Scratch (allocation-free __device__ globals). +DM pad for prefetch overread.
__device__ __align__(16) float g_Tw[BB * TE * DM + DM];   // tanh(enc @ W_a)
__device__ __align__(16) float g_Vw[BB * TE * DM + DM];   // v ⊙ tanh(enc @ W_a)
__device__ __align__(16) float g_Tu[BB * TD * DM];        // tanh(dec @ U_a)

// Fast accurate-enough tanh: 1 - 2/(exp(2x)+1). ~1e-7 rel err.
__device__ __forceinline__ float fast_tanhf(float x) {
    float ex = __expf(2.0f * x);
    return 1.0f - __fdividef(2.0f, ex + 1.0f);
}

// ---- Blackwell packed f32x2 helpers ----
typedef unsigned long long ull;
__device__ __forceinline__ ull pack2(float lo, float hi) {
    ull r; asm("mov.b64 %0, {%1, %2};" : "=l"(r) : "f"(lo), "f"(hi)); return r;
}
__device__ __forceinline__ float2 unpack2(ull v) {
    float2 r; asm("mov.b64 {%0, %1}, %2;" : "=f"(r.x), "=f"(r.y) : "l"(v)); return r;
}
__device__ __forceinline__ ull fma2(ull a, ull b, ull c) {
    ull d; asm("fma.rn.f32x2 %0, %1, %2, %3;" : "=l"(d) : "l"(a), "l"(b), "l"(c)); return d;
}
__device__ __forceinline__ float frcp(float x) {
    float y; asm("rcp.approx.ftz.f32 %0, %1;" : "=f"(y) : "f"(x)); return y;
}

// ---------------------------------------------------------------------------
// Combined projection GEMM (enc@W_a and dec@U_a in one launch).
// BM=32, BN=64, BK=16, 256 threads, 2x4/thread, double-buffered; 384 CTAs.
// Epilogue: fast tanh -> g_Tw/g_Tu; for Tw rows also g_Vw = tanh * v.
// ---------------------------------------------------------------------------
__global__ void __launch_bounds__(256)
proj_gemm2(const float* __restrict__ enc, const float* __restrict__ dec,
           const float* __restrict__ Wa,  const float* __restrict__ Ua,
           const float* __restrict__ Va) {
    __shared__ float sA[2][16][32];   // sA[p][k][m]
    __shared__ float sB[2][16][64];   // sB[p][k][n]

    const int tid = threadIdx.x;
    const int tx = tid & 15;          // n-sub (4 cols)
    const int ty = tid >> 4;          // m-sub (2 rows)
    const int row0 = blockIdx.x * 32;
    const int n0   = blockIdx.y * 64;

    const bool isW = (row0 < BB * TE);
    const float* X;
    const float* W;
    float* Y;
    if (isW) {
        X = enc + (size_t)row0 * DM;  W = Wa;  Y = g_Tw + (size_t)row0 * DM;
    } else {
        const int r = row0 - BB * TE;
        X = dec + (size_t)r * DM;     W = Ua;  Y = g_Tu + (size_t)r * DM;
    }

    float acc[2][4];
#pragma unroll
    for (int i = 0; i < 2; i++)
#pragma unroll
        for (int j = 0; j < 4; j++) acc[i][j] = 0.f;

    const int am  = tid >> 3;         // 0..31 (A m-row)
    const int akd = (tid & 7) * 2;    // 0..14 (A k pair)
    const int lr  = tid >> 4;         // 0..15 (B k-row)
    const int lc  = (tid & 15) * 4;   // B n-chunk

    // prologue: tile 0
    float2 av = *(const float2*)(X + am * DM + akd);
    float4 bv = *(const float4*)(W + lr * DM + n0 + lc);
    sA[0][akd][am]     = av.x;
    sA[0][akd + 1][am] = av.y;
    *(float4*)(&sB[0][lr][lc]) = bv;
    __syncthreads();

    int p = 0;
#pragma unroll 1
    for (int kt = 0; kt < 16; kt++) {
        float2 av2; float4 bv2;
        if (kt < 15) {
            av2 = *(const float2*)(X + am * DM + (kt + 1) * 16 + akd);
            bv2 = *(const float4*)(W + ((kt + 1) * 16 + lr) * DM + n0 + lc);
        }
#pragma unroll
        for (int kk = 0; kk < 16; kk++) {
            float2 a = *(const float2*)(&sA[p][kk][ty * 2]);
            float4 b = *(const float4*)(&sB[p][kk][tx * 4]);
            acc[0][0] = fmaf(a.x, b.x, acc[0][0]);
            acc[0][1] = fmaf(a.x, b.y, acc[0][1]);
            acc[0][2] = fmaf(a.x, b.z, acc[0][2]);
            acc[0][3] = fmaf(a.x, b.w, acc[0][3]);
            acc[1][0] = fmaf(a.y, b.x, acc[1][0]);
            acc[1][1] = fmaf(a.y, b.y, acc[1][1]);
            acc[1][2] = fmaf(a.y, b.z, acc[1][2]);
            acc[1][3] = fmaf(a.y, b.w, acc[1][3]);
        }
        if (kt < 15) {
            sA[p ^ 1][akd][am]     = av2.x;
            sA[p ^ 1][akd + 1][am] = av2.y;
            *(float4*)(&sB[p ^ 1][lr][lc]) = bv2;
        }
        __syncthreads();
        p ^= 1;
    }

    // Epilogue: fast tanh; Tw rows also store v-folded copy.
    float4 v4 = make_float4(0.f, 0.f, 0.f, 0.f);
    if (isW) v4 = *(const float4*)(Va + n0 + tx * 4);
#pragma unroll
    for (int i = 0; i < 2; i++) {
        float4 th = make_float4(fast_tanhf(acc[i][0]), fast_tanhf(acc[i][1]),
                                fast_tanhf(acc[i][2]), fast_tanhf(acc[i][3]));
        const size_t off = (size_t)(ty * 2 + i) * DM + n0 + tx * 4;
        *(float4*)(Y + off) = th;
        if (isW) {
            float4 vw = make_float4(th.x * v4.x, th.y * v4.y,
                                    th.z * v4.z, th.w * v4.w);
            *(float4*)(g_Vw + (size_t)row0 * DM + off) = vw;
        }
    }
}

// ---------------------------------------------------------------------------
// Score kernel: tanh-addition identity, paired rcp + packed f32x2.
// Grid: B * (TD/TT) = 256 CTAs, 256 threads (8 warps), ~2 CTAs/SM resident.
// Warp w -> e-block [w*64, (w+1)*64), all 4 t's per tw-load (4x reuse).
// Lane owns 8 d's (4 f32x2 packs). Per 2 elems:
//   den2=fma2(tw,tu,1); nv2=fma2(v,tu,vw); p=d0*d1; rp=rcp(p);
//   r2={rp*d1, rp*d0}; acc2=fma2(nv2, r2, acc2).   -> 6 cyc/elem fma-bound.
// ---------------------------------------------------------------------------
__global__ void __launch_bounds__(256)
attn_score(const float* __restrict__ Va, float* __restrict__ out_attn) {
    __shared__ __align__(16) float s_tu[TT * DM];          // 4 KB
    __shared__ __align__(16) float s_v[DM];                // 1 KB
    __shared__ __align__(16) float s_score[TE][TT];        // 8 KB, e-major

    const int b    = blockIdx.x >> 6;
    const int t0   = (blockIdx.x & 63) * TT;
    const int tid  = threadIdx.x;
    const int warp = tid >> 5;
    const int lane = tid & 31;

    // ---- Phase A: stage Tu rows + V ----
    ((float4*)s_tu)[tid] = ((const float4*)(g_Tu + (size_t)(b * TD + t0) * DM))[tid];
    if (tid < 64)
        ((float4*)s_v)[tid] = ((const float4*)Va)[tid];
    __syncthreads();

    // ---- Phase B: scores ----
    {
        const int dl = lane * 8;          // d-base
        const int eb = warp * 64;         // e-block

        ull tu2[4][4];
#pragma unroll
        for (int t = 0; t < 4; t++) {
            float4 q0 = *(const float4*)(s_tu + t * DM + dl);
            float4 q1 = *(const float4*)(s_tu + t * DM + dl + 4);
            tu2[t][0] = pack2(q0.x, q0.y);
            tu2[t][1] = pack2(q0.z, q0.w);
            tu2[t][2] = pack2(q1.x, q1.y);
            tu2[t][3] = pack2(q1.z, q1.w);
        }
        ull v2[4];
        {
            float4 q0 = *(const float4*)(s_v + dl);
            float4 q1 = *(const float4*)(s_v + dl + 4);
            v2[0] = pack2(q0.x, q0.y);
            v2[1] = pack2(q0.z, q0.w);
            v2[2] = pack2(q1.x, q1.y);
            v2[3] = pack2(q1.z, q1.w);
        }
        const ull ONE2  = pack2(1.0f, 1.0f);
        const ull ZERO2 = pack2(0.0f, 0.0f);

        const float* wr = g_Tw + ((size_t)(b * TE) + eb) * DM + dl;
        const float* vr = g_Vw + ((size_t)(b * TE) + eb) * DM + dl;
        float4 cw0 = *(const float4*)(wr);
        float4 cw1 = *(const float4*)(wr + 4);
        float4 cv0 = *(const float4*)(vr);
        float4 cv1 = *(const float4*)(vr + 4);

#pragma unroll 1
        for (int it = 0; it < 64; it++) {
            // prefetch next e-row (pad overread on final iter; values unused)
            wr += DM; vr += DM;
            float4 nw0 = *(const float4*)(wr);
            float4 nw1 = *(const float4*)(wr + 4);
            float4 nv0 = *(const float4*)(vr);
            float4 nv1 = *(const float4*)(vr + 4);

            ull tw2[4], vw2[4];
            tw2[0] = pack2(cw0.x, cw0.y); tw2[1] = pack2(cw0.z, cw0.w);
            tw2[2] = pack2(cw1.x, cw1.y); tw2[3] = pack2(cw1.z, cw1.w);
            vw2[0] = pack2(cv0.x, cv0.y); vw2[1] = pack2(cv0.z, cv0.w);
            vw2[2] = pack2(cv1.x, cv1.y); vw2[3] = pack2(cv1.z, cv1.w);

            float s4[4];
#pragma unroll
            for (int t = 0; t < 4; t++) {
                ull acc = ZERO2;
#pragma unroll
                for (int jp = 0; jp < 4; jp++) {
                    ull den2 = fma2(tw2[jp], tu2[t][jp], ONE2);
                    ull nv2  = fma2(v2[jp], tu2[t][jp], vw2[jp]);
                    float2 dd = unpack2(den2);
                    float p  = dd.x * dd.y;
                    float rp = frcp(p);
                    ull r2 = pack2(rp * dd.y, rp * dd.x);
                    acc = fma2(nv2, r2, acc);
                }
                float2 af = unpack2(acc);
                s4[t] = af.x + af.y;
            }
            // butterfly over all 32 lanes (d fully reduced)
#pragma unroll
            for (int off = 16; off > 0; off >>= 1) {
                s4[0] += __shfl_xor_sync(0xffffffffu, s4[0], off);
                s4[1] += __shfl_xor_sync(0xffffffffu, s4[1], off);
                s4[2] += __shfl_xor_sync(0xffffffffu, s4[2], off);
                s4[3] += __shfl_xor_sync(0xffffffffu, s4[3], off);
            }
            if (lane == 0)
                *(float4*)(&s_score[eb + it][0]) = make_float4(s4[0], s4[1], s4[2], s4[3]);

            cw0 = nw0; cw1 = nw1; cv0 = nv0; cv1 = nv1;
        }
    }
    __syncthreads();

    // ---- Phase C: softmax over e (warps 0..3, one t each), write attn ----
    if (warp < TT) {
        const int t = warp;
        float vals[16];
        float mx = -1e30f;
#pragma unroll
        for (int k = 0; k < 16; k++) {
            vals[k] = s_score[lane + 32 * k][t];
            mx = fmaxf(mx, vals[k]);
        }
#pragma unroll
        for (int off = 16; off > 0; off >>= 1)
            mx = fmaxf(mx, __shfl_xor_sync(0xffffffffu, mx, off));
        float sum = 0.f;
#pragma unroll
        for (int k = 0; k < 16; k++) {
            vals[k] = exp2f((vals[k] - mx) * 1.4426950408889634f);
            sum += vals[k];
        }
#pragma unroll
        for (int off = 16; off > 0; off >>= 1)
            sum += __shfl_xor_sync(0xffffffffu, sum, off);
        const float inv = 1.0f / sum;
        float* arow = out_attn + ((size_t)(b * TD + t0 + t)) * TE;
#pragma unroll
        for (int k = 0; k < 16; k++)
            arow[lane + 32 * k] = vals[k] * inv;
    }
}

// ---------------------------------------------------------------------------
// Context GEMM: ctx[b,t,d] = sum_e attn[b,t,e] * enc[b,e,d].
// BM=32 (t), BN=64 (d), BK=32 (e). 256 threads, thread = 2m x 4n.
// ---------------------------------------------------------------------------
__global__ void __launch_bounds__(256)
attn_ctx(const float* __restrict__ enc, const float* __restrict__ attn,
         float* __restrict__ out_ctx) {
    __shared__ float sAttT[32][32];   // [e][t] (transposed on store)
    __shared__ float sEnc[32][64];    // [e][d]

    const int b  = blockIdx.z;
    const int t0 = blockIdx.x * 32;
    const int d0 = blockIdx.y * 64;
    const int tid = threadIdx.x;
    const int tx = tid & 15;          // n-sub (4 d's)
    const int ty = tid >> 4;          // m-sub (2 t's)

    const float* attb = attn + ((size_t)(b * TD + t0)) * TE;
    const float* encb = enc + (size_t)b * TE * DM;

    float acc[2][4];
#pragma unroll
    for (int i = 0; i < 2; i++)
#pragma unroll
        for (int j = 0; j < 4; j++) acc[i][j] = 0.f;

    const int am = tid >> 3;          // 0..31 t-row for attn load
    const int ak = (tid & 7) * 4;     // e-chunk
    const int er = tid >> 4;          // 0..15 e-row for enc load
    const int ec = (tid & 15) * 4;    // d-chunk

#pragma unroll 1
    for (int k0 = 0; k0 < TE; k0 += 32) {
        float4 a = *(const float4*)(attb + (size_t)am * TE + k0 + ak);
        float4 e0 = *(const float4*)(encb + (size_t)(k0 + er) * DM + d0 + ec);
        float4 e1 = *(const float4*)(encb + (size_t)(k0 + 16 + er) * DM + d0 + ec);
        sAttT[ak + 0][am] = a.x;
        sAttT[ak + 1][am] = a.y;
        sAttT[ak + 2][am] = a.z;
        sAttT[ak + 3][am] = a.w;
        *(float4*)(&sEnc[er][ec])      = e0;
        *(float4*)(&sEnc[16 + er][ec]) = e1;
        __syncthreads();

#pragma unroll
        for (int k = 0; k < 32; k++) {
            float2 av2 = *(const float2*)(&sAttT[k][ty * 2]);
            float4 bv = *(const float4*)(&sEnc[k][tx * 4]);
            acc[0][0] = fmaf(av2.x, bv.x, acc[0][0]);
            acc[0][1] = fmaf(av2.x, bv.y, acc[0][1]);
            acc[0][2] = fmaf(av2.x, bv.z, acc[0][2]);
            acc[0][3] = fmaf(av2.x, bv.w, acc[0][3]);
            acc[1][0] = fmaf(av2.y, bv.x, acc[1][0]);
            acc[1][1] = fmaf(av2.y, bv.y, acc[1][1]);
            acc[1][2] = fmaf(av2.y, bv.z, acc[1][2]);
            acc[1][3] = fmaf(av2.y, bv.w, acc[1][3]);
        }
        __syncthreads();
    }

#pragma unroll
    for (int i = 0; i < 2; i++) {
        float4 o = make_float4(acc[i][0], acc[i][1], acc[i][2], acc[i][3]);
        *(float4*)(out_ctx + ((size_t)(b * TD + t0 + ty * 2 + i)) * DM + d0 + tx * 4) = o;
    }
}

extern "C" void kernel_launch(void* const* d_in, const int* in_sizes, int n_in,
                              void* d_out, int out_size) {
    const float* enc = (const float*)d_in[0];   // [4,512,256]
    const float* dec = (const float*)d_in[1];   // [4,256,256]
    const float* Wa  = (const float*)d_in[2];   // [256,256]
    const float* Ua  = (const float*)d_in[3];   // [256,256]
    const float* Va  = (const float*)d_in[4];   // [256,1]

    float* out      = (float*)d_out;
    float* out_ctx  = out;                          // [4,256,256]
    float* out_attn = out + (size_t)BB * TD * DM;   // [4,256,512]

    // Projections + tanh (+ v-fold) epilogue: 384 CTAs
    proj_gemm2<<<dim3((BB * TE + BB * TD) / 32, DM / 64), 256>>>(enc, dec, Wa, Ua, Va);

    // Scores + softmax: 256 CTAs x 256 threads
    attn_score<<<BB * (TD / TT), 256>>>(Va, out_attn);

    // Context GEMM: 128 CTAs
    attn_ctx<<<dim3(TD / 32, DM / 64, BB), 256>>>(enc, out_attn, out_ctx);
}

// round 10
// speedup vs baseline: 1.2090x; 1.0114x over previous
#include <cuda_runtime.h>
#include <cuda_bf16.h>
#include <math.h>

// Problem dims (fixed by reference setup_inputs)
#define BB 4
#define TE 512
#define TD 256
#define DM 256
#define TT 4   // t-rows per CTA in score kernel

// Scratch (allocation-free __device__ globals). +DM pad for prefetch overread.
__device__ __align__(16) float g_Tw[BB * TE * DM + DM];   // tanh(enc @ W_a)
__device__ __align__(16) float g_Tu[BB * TD * DM];        // tanh(dec @ U_a)

// Fast accurate-enough tanh: 1 - 2/(exp(2x)+1). ~1e-7 rel err.
__device__ __forceinline__ float fast_tanhf(float x) {
    float ex = __expf(2.0f * x);
    return 1.0f - __fdividef(2.0f, ex + 1.0f);
}

__device__ __forceinline__ float frcp(float x) {
    float y; asm("rcp.approx.ftz.f32 %0, %1;" : "=f"(y) : "f"(x)); return y;
}

// ---------------------------------------------------------------------------
// Combined projection GEMM (enc@W_a and dec@U_a in one launch).
// BM=128, BN=64, BK=16, 512 threads, 4x4/thread, double-buffered SMEM.
// grid = (24, 4) = 96 CTAs -> SINGLE WAVE on 148 SMs (no quantization tail).
// Row tiles 0..15 -> enc (2048 rows), 16..23 -> dec (1024 rows); 2048%128==0.
// Epilogue: fast tanh -> g_Tw / g_Tu (f32).
// ---------------------------------------------------------------------------
__global__ void __launch_bounds__(512)
proj_gemm2(const float* __restrict__ enc, const float* __restrict__ dec,
           const float* __restrict__ Wa,  const float* __restrict__ Ua) {
    __shared__ float sA[2][16][128];  // sA[p][k][m]  16 KB
    __shared__ float sB[2][16][64];   // sB[p][k][n]   8 KB

    const int tid = threadIdx.x;
    const int tx = tid & 15;          // n-sub (0..15)
    const int ty = tid >> 4;          // m-sub (0..31)
    const int row0 = blockIdx.x * 128;
    const int n0   = blockIdx.y * 64;

    const float* X;
    const float* W;
    float* Y;
    if (row0 < BB * TE) {
        X = enc + (size_t)row0 * DM;  W = Wa;  Y = g_Tw + (size_t)row0 * DM;
    } else {
        const int r = row0 - BB * TE;
        X = dec + (size_t)r * DM;     W = Ua;  Y = g_Tu + (size_t)r * DM;
    }

    float acc[4][4];
#pragma unroll
    for (int i = 0; i < 4; i++)
#pragma unroll
        for (int j = 0; j < 4; j++) acc[i][j] = 0.f;

    const int lm  = tid >> 2;         // 0..127 (A m-row)
    const int lkq = tid & 3;          // 0..3   (A k quad)
    const int lr  = tid >> 5;         // 0..15  (B k-row)
    const int lc  = (tid & 31) * 2;   // B n-chunk (float2)

    // prologue: tile 0
    float4 av = *(const float4*)(X + lm * DM + 4 * lkq);
    float2 bv = *(const float2*)(W + lr * DM + n0 + lc);
    sA[0][4 * lkq + 0][lm] = av.x;
    sA[0][4 * lkq + 1][lm] = av.y;
    sA[0][4 * lkq + 2][lm] = av.z;
    sA[0][4 * lkq + 3][lm] = av.w;
    *(float2*)(&sB[0][lr][lc]) = bv;
    __syncthreads();

    int p = 0;
#pragma unroll 1
    for (int kt = 0; kt < 16; kt++) {
        float4 av2; float2 bv2;
        if (kt < 15) {
            av2 = *(const float4*)(X + lm * DM + (kt + 1) * 16 + 4 * lkq);
            bv2 = *(const float2*)(W + ((kt + 1) * 16 + lr) * DM + n0 + lc);
        }
#pragma unroll
        for (int kk = 0; kk < 16; kk++) {
            float4 a = *(const float4*)(&sA[p][kk][ty * 4]);
            float4 b = *(const float4*)(&sB[p][kk][tx * 4]);
            acc[0][0] = fmaf(a.x, b.x, acc[0][0]);
            acc[0][1] = fmaf(a.x, b.y, acc[0][1]);
            acc[0][2] = fmaf(a.x, b.z, acc[0][2]);
            acc[0][3] = fmaf(a.x, b.w, acc[0][3]);
            acc[1][0] = fmaf(a.y, b.x, acc[1][0]);
            acc[1][1] = fmaf(a.y, b.y, acc[1][1]);
            acc[1][2] = fmaf(a.y, b.z, acc[1][2]);
            acc[1][3] = fmaf(a.y, b.w, acc[1][3]);
            acc[2][0] = fmaf(a.z, b.x, acc[2][0]);
            acc[2][1] = fmaf(a.z, b.y, acc[2][1]);
            acc[2][2] = fmaf(a.z, b.z, acc[2][2]);
            acc[2][3] = fmaf(a.z, b.w, acc[2][3]);
            acc[3][0] = fmaf(a.w, b.x, acc[3][0]);
            acc[3][1] = fmaf(a.w, b.y, acc[3][1]);
            acc[3][2] = fmaf(a.w, b.z, acc[3][2]);
            acc[3][3] = fmaf(a.w, b.w, acc[3][3]);
        }
        if (kt < 15) {
            sA[p ^ 1][4 * lkq + 0][lm] = av2.x;
            sA[p ^ 1][4 * lkq + 1][lm] = av2.y;
            sA[p ^ 1][4 * lkq + 2][lm] = av2.z;
            sA[p ^ 1][4 * lkq + 3][lm] = av2.w;
            *(float2*)(&sB[p ^ 1][lr][lc]) = bv2;
        }
        __syncthreads();
        p ^= 1;
    }

    // Epilogue: fast tanh, store f32
#pragma unroll
    for (int i = 0; i < 4; i++) {
        float4 o = make_float4(fast_tanhf(acc[i][0]), fast_tanhf(acc[i][1]),
                               fast_tanhf(acc[i][2]), fast_tanhf(acc[i][3]));
        *(float4*)(Y + (size_t)(ty * 4 + i) * DM + n0 + tx * 4) = o;
    }
}

// ---------------------------------------------------------------------------
// Score kernel, minimal-op identity + softmax shift-invariance:
//   tanh(w+u) = tu + tw*(1-tu^2)/(1+tw*tu);  sum_d v*tu is constant per (b,t)
//   and cancels in softmax, so  score'[t,e] = sum_d c[t,d]*tw/(1+tw*tu),
//   with c = v*(1-tu^2) precomputed in SMEM.
// Per element: den=fma(tw,tu,1); q=tw*rcp(den); acc=fma(c,q,acc)
//   -> 3 fma-pipe + 1 MUFU.RCP (rt=8) per lane-elem. MUFU-bound ~30us chip.
// Grid: 256 CTAs x 256 threads; tu/c in SMEM (low regs -> 4+ CTAs/SM).
// Warp w -> e-block [w*64,(w+1)*64); lane owns 8 d's; 4 t per tw-load.
// ---------------------------------------------------------------------------
__global__ void __launch_bounds__(256)
attn_score(const float* __restrict__ Va, float* __restrict__ out_attn) {
    __shared__ __align__(16) float s_tu[TT * DM];          // 4 KB
    __shared__ __align__(16) float s_c[TT * DM];           // 4 KB
    __shared__ __align__(16) float s_score[TE][TT];        // 8 KB, e-major

    const int b    = blockIdx.x >> 6;
    const int t0   = (blockIdx.x & 63) * TT;
    const int tid  = threadIdx.x;
    const int warp = tid >> 5;
    const int lane = tid & 31;

    // ---- Phase A: stage tu and c = v*(1 - tu^2) ----
    {
        float4 tu4 = ((const float4*)(g_Tu + (size_t)(b * TD + t0) * DM))[tid];
        float4 v4  = ((const float4*)Va)[tid & 63];
        ((float4*)s_tu)[tid] = tu4;
        float4 c4;
        c4.x = fmaf(-v4.x * tu4.x, tu4.x, v4.x);
        c4.y = fmaf(-v4.y * tu4.y, tu4.y, v4.y);
        c4.z = fmaf(-v4.z * tu4.z, tu4.z, v4.z);
        c4.w = fmaf(-v4.w * tu4.w, tu4.w, v4.w);
        ((float4*)s_c)[tid] = c4;
    }
    __syncthreads();

    // ---- Phase B: scores ----
    {
        const int dl = lane * 8;          // d-base for this lane
        const int eb = warp * 64;         // e-block

        const float* wr = g_Tw + ((size_t)(b * TE) + eb) * DM + dl;
        float cur[8];
        *(float4*)(&cur[0]) = *(const float4*)(wr);
        *(float4*)(&cur[4]) = *(const float4*)(wr + 4);

#pragma unroll 1
        for (int it = 0; it < 64; it++) {
            // prefetch next e-row (pad overread on final iter; values unused)
            wr += DM;
            float nxt[8];
            *(float4*)(&nxt[0]) = *(const float4*)(wr);
            *(float4*)(&nxt[4]) = *(const float4*)(wr + 4);

            float s4[4];
#pragma unroll
            for (int t = 0; t < 4; t++) {
                float4 ua = *(const float4*)(s_tu + t * DM + dl);
                float4 ub = *(const float4*)(s_tu + t * DM + dl + 4);
                float4 ca = *(const float4*)(s_c + t * DM + dl);
                float4 cb = *(const float4*)(s_c + t * DM + dl + 4);
                float a0 = 0.f, a1 = 0.f, den, q;
                den = fmaf(cur[0], ua.x, 1.f); q = cur[0] * frcp(den); a0 = fmaf(ca.x, q, a0);
                den = fmaf(cur[1], ua.y, 1.f); q = cur[1] * frcp(den); a1 = fmaf(ca.y, q, a1);
                den = fmaf(cur[2], ua.z, 1.f); q = cur[2] * frcp(den); a0 = fmaf(ca.z, q, a0);
                den = fmaf(cur[3], ua.w, 1.f); q = cur[3] * frcp(den); a1 = fmaf(ca.w, q, a1);
                den = fmaf(cur[4], ub.x, 1.f); q = cur[4] * frcp(den); a0 = fmaf(cb.x, q, a0);
                den = fmaf(cur[5], ub.y, 1.f); q = cur[5] * frcp(den); a1 = fmaf(cb.y, q, a1);
                den = fmaf(cur[6], ub.z, 1.f); q = cur[6] * frcp(den); a0 = fmaf(cb.z, q, a0);
                den = fmaf(cur[7], ub.w, 1.f); q = cur[7] * frcp(den); a1 = fmaf(cb.w, q, a1);
                s4[t] = a0 + a1;
            }
            // butterfly over all 32 lanes (d fully reduced)
#pragma unroll
            for (int off = 16; off > 0; off >>= 1) {
                s4[0] += __shfl_xor_sync(0xffffffffu, s4[0], off);
                s4[1] += __shfl_xor_sync(0xffffffffu, s4[1], off);
                s4[2] += __shfl_xor_sync(0xffffffffu, s4[2], off);
                s4[3] += __shfl_xor_sync(0xffffffffu, s4[3], off);
            }
            if (lane == 0)
                *(float4*)(&s_score[eb + it][0]) = make_float4(s4[0], s4[1], s4[2], s4[3]);

#pragma unroll
            for (int j = 0; j < 8; j++) cur[j] = nxt[j];
        }
    }
    __syncthreads();

    // ---- Phase C: softmax over e (warps 0..3, one t each), write attn ----
    // (shifted scores: softmax is invariant to the dropped per-t constant)
    if (warp < TT) {
        const int t = warp;
        float vals[16];
        float mx = -1e30f;
#pragma unroll
        for (int k = 0; k < 16; k++) {
            vals[k] = s_score[lane + 32 * k][t];
            mx = fmaxf(mx, vals[k]);
        }
#pragma unroll
        for (int off = 16; off > 0; off >>= 1)
            mx = fmaxf(mx, __shfl_xor_sync(0xffffffffu, mx, off));
        float sum = 0.f;
#pragma unroll
        for (int k = 0; k < 16; k++) {
            vals[k] = exp2f((vals[k] - mx) * 1.4426950408889634f);
            sum += vals[k];
        }
#pragma unroll
        for (int off = 16; off > 0; off >>= 1)
            sum += __shfl_xor_sync(0xffffffffu, sum, off);
        const float inv = 1.0f / sum;
        float* arow = out_attn + ((size_t)(b * TD + t0 + t)) * TE;
#pragma unroll
        for (int k = 0; k < 16; k++)
            arow[lane + 32 * k] = vals[k] * inv;
    }
}

// ---------------------------------------------------------------------------
// Context GEMM: ctx[b,t,d] = sum_e attn[b,t,e] * enc[b,e,d].
// BM=32 (t), BN=64 (d), BK=32 (e). 256 threads, thread = 2m x 4n.
// ---------------------------------------------------------------------------
__global__ void __launch_bounds__(256)
attn_ctx(const float* __restrict__ enc, const float* __restrict__ attn,
         float* __restrict__ out_ctx) {
    __shared__ float sAttT[32][32];   // [e][t] (transposed on store)
    __shared__ float sEnc[32][64];    // [e][d]

    const int b  = blockIdx.z;
    const int t0 = blockIdx.x * 32;
    const int d0 = blockIdx.y * 64;
    const int tid = threadIdx.x;
    const int tx = tid & 15;          // n-sub (4 d's)
    const int ty = tid >> 4;          // m-sub (2 t's)

    const float* attb = attn + ((size_t)(b * TD + t0)) * TE;
    const float* encb = enc + (size_t)b * TE * DM;

    float acc[2][4];
#pragma unroll
    for (int i = 0; i < 2; i++)
#pragma unroll
        for (int j = 0; j < 4; j++) acc[i][j] = 0.f;

    const int am = tid >> 3;          // 0..31 t-row for attn load
    const int ak = (tid & 7) * 4;     // e-chunk
    const int er = tid >> 4;          // 0..15 e-row for enc load
    const int ec = (tid & 15) * 4;    // d-chunk

#pragma unroll 1
    for (int k0 = 0; k0 < TE; k0 += 32) {
        float4 a = *(const float4*)(attb + (size_t)am * TE + k0 + ak);
        float4 e0 = *(const float4*)(encb + (size_t)(k0 + er) * DM + d0 + ec);
        float4 e1 = *(const float4*)(encb + (size_t)(k0 + 16 + er) * DM + d0 + ec);
        sAttT[ak + 0][am] = a.x;
        sAttT[ak + 1][am] = a.y;
        sAttT[ak + 2][am] = a.z;
        sAttT[ak + 3][am] = a.w;
        *(float4*)(&sEnc[er][ec])      = e0;
        *(float4*)(&sEnc[16 + er][ec]) = e1;
        __syncthreads();

#pragma unroll
        for (int k = 0; k < 32; k++) {
            float2 av2 = *(const float2*)(&sAttT[k][ty * 2]);
            float4 bv = *(const float4*)(&sEnc[k][tx * 4]);
            acc[0][0] = fmaf(av2.x, bv.x, acc[0][0]);
            acc[0][1] = fmaf(av2.x, bv.y, acc[0][1]);
            acc[0][2] = fmaf(av2.x, bv.z, acc[0][2]);
            acc[0][3] = fmaf(av2.x, bv.w, acc[0][3]);
            acc[1][0] = fmaf(av2.y, bv.x, acc[1][0]);
            acc[1][1] = fmaf(av2.y, bv.y, acc[1][1]);
            acc[1][2] = fmaf(av2.y, bv.z, acc[1][2]);
            acc[1][3] = fmaf(av2.y, bv.w, acc[1][3]);
        }
        __syncthreads();
    }

#pragma unroll
    for (int i = 0; i < 2; i++) {
        float4 o = make_float4(acc[i][0], acc[i][1], acc[i][2], acc[i][3]);
        *(float4*)(out_ctx + ((size_t)(b * TD + t0 + ty * 2 + i)) * DM + d0 + tx * 4) = o;
    }
}

extern "C" void kernel_launch(void* const* d_in, const int* in_sizes, int n_in,
                              void* d_out, int out_size) {
    const float* enc = (const float*)d_in[0];   // [4,512,256]
    const float* dec = (const float*)d_in[1];   // [4,256,256]
    const float* Wa  = (const float*)d_in[2];   // [256,256]
    const float* Ua  = (const float*)d_in[3];   // [256,256]
    const float* Va  = (const float*)d_in[4];   // [256,1]

    float* out      = (float*)d_out;
    float* out_ctx  = out;                          // [4,256,256]
    float* out_attn = out + (size_t)BB * TD * DM;   // [4,256,512]

    // Projections + tanh epilogue: 96 CTAs (single wave)
    proj_gemm2<<<dim3((BB * TE + BB * TD) / 128, DM / 64), 512>>>(enc, dec, Wa, Ua);

    // Scores + softmax: 256 CTAs x 256 threads
    attn_score<<<BB * (TD / TT), 256>>>(Va, out_attn);

    // Context GEMM: 128 CTAs
    attn_ctx<<<dim3(TD / 32, DM / 64, BB), 256>>>(enc, out_attn, out_ctx);
}

// round 11
// speedup vs baseline: 1.2112x; 1.0018x over previous
#include <cuda_runtime.h>
#include <cuda_bf16.h>
#include <math.h>

// Problem dims (fixed by reference setup_inputs)
#define BB 4
#define TE 512
#define TD 256
#define DM 256
#define TT 4   // t-rows per CTA in score kernel

// Scratch (allocation-free __device__ globals). +DM pad for prefetch overread.
__device__ __align__(16) float g_Tw[BB * TE * DM + DM];   // tanh(enc @ W_a)
__device__ __align__(16) float g_Tu[BB * TD * DM];        // tanh(dec @ U_a)

// Fast accurate-enough tanh: 1 - 2/(exp(2x)+1). ~1e-7 rel err, strictly |.|<1.
__device__ __forceinline__ float fast_tanhf(float x) {
    float ex = __expf(2.0f * x);
    return 1.0f - __fdividef(2.0f, ex + 1.0f);
}

__device__ __forceinline__ float frcp(float x) {
    float y; asm("rcp.approx.ftz.f32 %0, %1;" : "=f"(y) : "f"(x)); return y;
}

// ---------------------------------------------------------------------------
// Combined projection GEMM (enc@W_a and dec@U_a in one launch).
// BM=64, BN=64, BK=16, 256 threads, 4x4/thread, double-buffered (R8 shape,
// measured 21.7us). Rows 0..2047 -> g_Tw, 2048..3071 -> g_Tu.
// ---------------------------------------------------------------------------
__global__ void __launch_bounds__(256)
proj_gemm2(const float* __restrict__ enc, const float* __restrict__ dec,
           const float* __restrict__ Wa,  const float* __restrict__ Ua) {
    __shared__ float sA[2][16][64];   // sA[p][k][m]
    __shared__ float sB[2][16][64];   // sB[p][k][n]

    const int tid = threadIdx.x;
    const int tx = tid & 15;          // n-sub
    const int ty = tid >> 4;          // m-sub
    const int row0 = blockIdx.x * 64;
    const int n0   = blockIdx.y * 64;

    const float* X;
    const float* W;
    float* Y;
    if (row0 < BB * TE) {
        X = enc + (size_t)row0 * DM;  W = Wa;  Y = g_Tw + (size_t)row0 * DM;
    } else {
        const int r = row0 - BB * TE;
        X = dec + (size_t)r * DM;     W = Ua;  Y = g_Tu + (size_t)r * DM;
    }

    float acc[4][4];
#pragma unroll
    for (int i = 0; i < 4; i++)
#pragma unroll
        for (int j = 0; j < 4; j++) acc[i][j] = 0.f;

    const int lm  = tid >> 2;         // 0..63
    const int lkq = tid & 3;          // 0..3
    const int lr  = tid >> 4;         // 0..15
    const int lc  = tid & 15;         // 0..15

    // prologue: tile 0
    float4 av = *(const float4*)(X + lm * DM + 4 * lkq);
    float4 bv = *(const float4*)(W + lr * DM + n0 + 4 * lc);
    sA[0][4 * lkq + 0][lm] = av.x;
    sA[0][4 * lkq + 1][lm] = av.y;
    sA[0][4 * lkq + 2][lm] = av.z;
    sA[0][4 * lkq + 3][lm] = av.w;
    *(float4*)(&sB[0][lr][4 * lc]) = bv;
    __syncthreads();

    int p = 0;
#pragma unroll 1
    for (int kt = 0; kt < 16; kt++) {
        float4 av2, bv2;
        if (kt < 15) {
            av2 = *(const float4*)(X + lm * DM + (kt + 1) * 16 + 4 * lkq);
            bv2 = *(const float4*)(W + ((kt + 1) * 16 + lr) * DM + n0 + 4 * lc);
        }
#pragma unroll
        for (int kk = 0; kk < 16; kk++) {
            float4 a = *(const float4*)(&sA[p][kk][ty * 4]);
            float4 b = *(const float4*)(&sB[p][kk][tx * 4]);
            acc[0][0] += a.x * b.x; acc[0][1] += a.x * b.y; acc[0][2] += a.x * b.z; acc[0][3] += a.x * b.w;
            acc[1][0] += a.y * b.x; acc[1][1] += a.y * b.y; acc[1][2] += a.y * b.z; acc[1][3] += a.y * b.w;
            acc[2][0] += a.z * b.x; acc[2][1] += a.z * b.y; acc[2][2] += a.z * b.z; acc[2][3] += a.z * b.w;
            acc[3][0] += a.w * b.x; acc[3][1] += a.w * b.y; acc[3][2] += a.w * b.z; acc[3][3] += a.w * b.w;
        }
        if (kt < 15) {
            sA[p ^ 1][4 * lkq + 0][lm] = av2.x;
            sA[p ^ 1][4 * lkq + 1][lm] = av2.y;
            sA[p ^ 1][4 * lkq + 2][lm] = av2.z;
            sA[p ^ 1][4 * lkq + 3][lm] = av2.w;
            *(float4*)(&sB[p ^ 1][lr][4 * lc]) = bv2;
        }
        __syncthreads();
        p ^= 1;
    }

    // Epilogue: fast tanh, store f32
#pragma unroll
    for (int i = 0; i < 4; i++) {
        float4 o = make_float4(fast_tanhf(acc[i][0]), fast_tanhf(acc[i][1]),
                               fast_tanhf(acc[i][2]), fast_tanhf(acc[i][3]));
        *(float4*)(Y + (ty * 4 + i) * DM + n0 + tx * 4) = o;
    }
}

// ---------------------------------------------------------------------------
// Score kernel, minimal-op identity, FULLY REGISTER-RESIDENT tu/c:
//   score'[t,e] = sum_d c[t,d]*tw/(1+tw*tu),  c = v*(1-tu^2)
//   (the dropped sum_d v*tu is constant per t and cancels in softmax).
// Per element: den=fma(tw,tu,1); q=tw*rcp(den); acc=fma(c,q,acc)
//   -> 3 fma-pipe + 1 MUFU.RCP; ZERO shared-memory reads in the loop.
// Grid: 256 CTAs x 256 threads (~2 CTAs/SM at ~100 regs).
// Warp w -> e-block [w*64,(w+1)*64); lane owns 8 d's; 4 t per tw-load.
// tu[4][8] + c[4][8] hoisted to 64 registers; w row double-buffered.
// ---------------------------------------------------------------------------
__global__ void __launch_bounds__(256)
attn_score(const float* __restrict__ Va, float* __restrict__ out_attn) {
    __shared__ __align__(16) float s_tu[TT * DM];          // 4 KB (staging)
    __shared__ __align__(16) float s_c[TT * DM];           // 4 KB (staging)
    __shared__ __align__(16) float s_score[TE][TT];        // 8 KB, e-major

    const int b    = blockIdx.x >> 6;
    const int t0   = (blockIdx.x & 63) * TT;
    const int tid  = threadIdx.x;
    const int warp = tid >> 5;
    const int lane = tid & 31;

    // ---- Phase A: stage tu and c = v*(1 - tu^2) via SMEM ----
    {
        float4 tu4 = ((const float4*)(g_Tu + (size_t)(b * TD + t0) * DM))[tid];
        float4 v4  = ((const float4*)Va)[tid & 63];
        ((float4*)s_tu)[tid] = tu4;
        float4 c4;
        c4.x = fmaf(-v4.x * tu4.x, tu4.x, v4.x);
        c4.y = fmaf(-v4.y * tu4.y, tu4.y, v4.y);
        c4.z = fmaf(-v4.z * tu4.z, tu4.z, v4.z);
        c4.w = fmaf(-v4.w * tu4.w, tu4.w, v4.w);
        ((float4*)s_c)[tid] = c4;
    }
    __syncthreads();

    // ---- Phase B: scores ----
    {
        const int dl = lane * 8;          // d-base for this lane
        const int eb = warp * 64;         // e-block

        // hoist tu and c for all 4 t's into registers (one-time LDS)
        float tu[4][8], c[4][8];
#pragma unroll
        for (int t = 0; t < 4; t++) {
            const float4* up = (const float4*)(s_tu + t * DM + dl);
            const float4* cp = (const float4*)(s_c  + t * DM + dl);
            *(float4*)(&tu[t][0]) = up[0];
            *(float4*)(&tu[t][4]) = up[1];
            *(float4*)(&c[t][0])  = cp[0];
            *(float4*)(&c[t][4])  = cp[1];
        }

        const float* wr = g_Tw + ((size_t)(b * TE) + eb) * DM + dl;
        float cur[8];
        *(float4*)(&cur[0]) = *(const float4*)(wr);
        *(float4*)(&cur[4]) = *(const float4*)(wr + 4);

#pragma unroll 1
        for (int it = 0; it < 64; it++) {
            // prefetch next e-row (pad overread on final iter; values unused)
            wr += DM;
            float nxt[8];
            *(float4*)(&nxt[0]) = *(const float4*)(wr);
            *(float4*)(&nxt[4]) = *(const float4*)(wr + 4);

            float s4[4];
#pragma unroll
            for (int t = 0; t < 4; t++) {
                float a0 = 0.f, a1 = 0.f;
#pragma unroll
                for (int j = 0; j < 8; j += 2) {
                    float d0 = fmaf(cur[j],     tu[t][j],     1.f);
                    float d1 = fmaf(cur[j + 1], tu[t][j + 1], 1.f);
                    float q0 = cur[j]     * frcp(d0);
                    float q1 = cur[j + 1] * frcp(d1);
                    a0 = fmaf(c[t][j],     q0, a0);
                    a1 = fmaf(c[t][j + 1], q1, a1);
                }
                s4[t] = a0 + a1;
            }
            // butterfly over all 32 lanes (d fully reduced)
#pragma unroll
            for (int off = 16; off > 0; off >>= 1) {
                s4[0] += __shfl_xor_sync(0xffffffffu, s4[0], off);
                s4[1] += __shfl_xor_sync(0xffffffffu, s4[1], off);
                s4[2] += __shfl_xor_sync(0xffffffffu, s4[2], off);
                s4[3] += __shfl_xor_sync(0xffffffffu, s4[3], off);
            }
            if (lane == 0)
                *(float4*)(&s_score[eb + it][0]) = make_float4(s4[0], s4[1], s4[2], s4[3]);

#pragma unroll
            for (int j = 0; j < 8; j++) cur[j] = nxt[j];
        }
    }
    __syncthreads();

    // ---- Phase C: softmax over e (warps 0..3, one t each), write attn ----
    if (warp < TT) {
        const int t = warp;
        float vals[16];
        float mx = -1e30f;
#pragma unroll
        for (int k = 0; k < 16; k++) {
            vals[k] = s_score[lane + 32 * k][t];
            mx = fmaxf(mx, vals[k]);
        }
#pragma unroll
        for (int off = 16; off > 0; off >>= 1)
            mx = fmaxf(mx, __shfl_xor_sync(0xffffffffu, mx, off));
        float sum = 0.f;
#pragma unroll
        for (int k = 0; k < 16; k++) {
            vals[k] = exp2f((vals[k] - mx) * 1.4426950408889634f);
            sum += vals[k];
        }
#pragma unroll
        for (int off = 16; off > 0; off >>= 1)
            sum += __shfl_xor_sync(0xffffffffu, sum, off);
        const float inv = 1.0f / sum;
        float* arow = out_attn + ((size_t)(b * TD + t0 + t)) * TE;
#pragma unroll
        for (int k = 0; k < 16; k++)
            arow[lane + 32 * k] = vals[k] * inv;
    }
}

// ---------------------------------------------------------------------------
// Context GEMM: ctx[b,t,d] = sum_e attn[b,t,e] * enc[b,e,d].
// BM=32 (t), BN=64 (d), BK=32 (e). 256 threads, thread = 2m x 4n.
// ---------------------------------------------------------------------------
__global__ void __launch_bounds__(256)
attn_ctx(const float* __restrict__ enc, const float* __restrict__ attn,
         float* __restrict__ out_ctx) {
    __shared__ float sAttT[32][32];   // [e][t] (transposed on store)
    __shared__ float sEnc[32][64];    // [e][d]

    const int b  = blockIdx.z;
    const int t0 = blockIdx.x * 32;
    const int d0 = blockIdx.y * 64;
    const int tid = threadIdx.x;
    const int tx = tid & 15;          // n-sub (4 d's)
    const int ty = tid >> 4;          // m-sub (2 t's)

    const float* attb = attn + ((size_t)(b * TD + t0)) * TE;
    const float* encb = enc + (size_t)b * TE * DM;

    float acc[2][4];
#pragma unroll
    for (int i = 0; i < 2; i++)
#pragma unroll
        for (int j = 0; j < 4; j++) acc[i][j] = 0.f;

    const int am = tid >> 3;          // 0..31 t-row for attn load
    const int ak = (tid & 7) * 4;     // e-chunk
    const int er = tid >> 4;          // 0..15 e-row for enc load
    const int ec = (tid & 15) * 4;    // d-chunk

#pragma unroll 1
    for (int k0 = 0; k0 < TE; k0 += 32) {
        float4 a = *(const float4*)(attb + (size_t)am * TE + k0 + ak);
        float4 e0 = *(const float4*)(encb + (size_t)(k0 + er) * DM + d0 + ec);
        float4 e1 = *(const float4*)(encb + (size_t)(k0 + 16 + er) * DM + d0 + ec);
        sAttT[ak + 0][am] = a.x;
        sAttT[ak + 1][am] = a.y;
        sAttT[ak + 2][am] = a.z;
        sAttT[ak + 3][am] = a.w;
        *(float4*)(&sEnc[er][ec])      = e0;
        *(float4*)(&sEnc[16 + er][ec]) = e1;
        __syncthreads();

#pragma unroll
        for (int k = 0; k < 32; k++) {
            float2 av2 = *(const float2*)(&sAttT[k][ty * 2]);
            float4 bv = *(const float4*)(&sEnc[k][tx * 4]);
            acc[0][0] = fmaf(av2.x, bv.x, acc[0][0]);
            acc[0][1] = fmaf(av2.x, bv.y, acc[0][1]);
            acc[0][2] = fmaf(av2.x, bv.z, acc[0][2]);
            acc[0][3] = fmaf(av2.x, bv.w, acc[0][3]);
            acc[1][0] = fmaf(av2.y, bv.x, acc[1][0]);
            acc[1][1] = fmaf(av2.y, bv.y, acc[1][1]);
            acc[1][2] = fmaf(av2.y, bv.z, acc[1][2]);
            acc[1][3] = fmaf(av2.y, bv.w, acc[1][3]);
        }
        __syncthreads();
    }

#pragma unroll
    for (int i = 0; i < 2; i++) {
        float4 o = make_float4(acc[i][0], acc[i][1], acc[i][2], acc[i][3]);
        *(float4*)(out_ctx + ((size_t)(b * TD + t0 + ty * 2 + i)) * DM + d0 + tx * 4) = o;
    }
}

extern "C" void kernel_launch(void* const* d_in, const int* in_sizes, int n_in,
                              void* d_out, int out_size) {
    const float* enc = (const float*)d_in[0];   // [4,512,256]
    const float* dec = (const float*)d_in[1];   // [4,256,256]
    const float* Wa  = (const float*)d_in[2];   // [256,256]
    const float* Ua  = (const float*)d_in[3];   // [256,256]
    const float* Va  = (const float*)d_in[4];   // [256,1]

    float* out      = (float*)d_out;
    float* out_ctx  = out;                          // [4,256,256]
    float* out_attn = out + (size_t)BB * TD * DM;   // [4,256,512]

    // Projections + tanh epilogue: 192 CTAs (measured-best shape)
    proj_gemm2<<<dim3((BB * TE + BB * TD) / 64, DM / 64), 256>>>(enc, dec, Wa, Ua);

    // Scores + softmax: 256 CTAs x 256 threads
    attn_score<<<BB * (TD / TT), 256>>>(Va, out_attn);

    // Context GEMM: 128 CTAs
    attn_ctx<<<dim3(TD / 32, DM / 64, BB), 256>>>(enc, out_attn, out_ctx);
}

// round 12
// speedup vs baseline: 1.3435x; 1.1092x over previous
#include <cuda_runtime.h>
#include <cuda_bf16.h>
#include <math.h>

// Problem dims (fixed by reference setup_inputs)
#define BB 4
#define TE 512
#define TD 256
#define DM 256
#define TT 4   // t-rows per CTA in score kernel

// Scratch (allocation-free __device__ globals). +DM pad for prefetch overread.
__device__ __align__(16) float g_Ew[BB * TE * DM + DM];   // exp(2 * enc @ W_a)
__device__ __align__(16) float g_Eu[BB * TD * DM];        // exp(2 * dec @ U_a)

__device__ __forceinline__ float frcp(float x) {
    float y; asm("rcp.approx.ftz.f32 %0, %1;" : "=f"(y) : "f"(x)); return y;
}

// ---------------------------------------------------------------------------
// Combined projection GEMM (enc@W_a and dec@U_a in one launch).
// BM=64, BN=64, BK=16, 256 threads, 4x4/thread, double-buffered (measured-best
// shape, 21.4us). Rows 0..2047 -> g_Ew, 2048..3071 -> g_Eu.
// Epilogue stores exp(2*acc) (for the tanh exp-identity in attn_score).
// ---------------------------------------------------------------------------
__global__ void __launch_bounds__(256)
proj_gemm2(const float* __restrict__ enc, const float* __restrict__ dec,
           const float* __restrict__ Wa,  const float* __restrict__ Ua) {
    __shared__ float sA[2][16][64];   // sA[p][k][m]
    __shared__ float sB[2][16][64];   // sB[p][k][n]

    const int tid = threadIdx.x;
    const int tx = tid & 15;          // n-sub
    const int ty = tid >> 4;          // m-sub
    const int row0 = blockIdx.x * 64;
    const int n0   = blockIdx.y * 64;

    const float* X;
    const float* W;
    float* Y;
    if (row0 < BB * TE) {
        X = enc + (size_t)row0 * DM;  W = Wa;  Y = g_Ew + (size_t)row0 * DM;
    } else {
        const int r = row0 - BB * TE;
        X = dec + (size_t)r * DM;     W = Ua;  Y = g_Eu + (size_t)r * DM;
    }

    float acc[4][4];
#pragma unroll
    for (int i = 0; i < 4; i++)
#pragma unroll
        for (int j = 0; j < 4; j++) acc[i][j] = 0.f;

    const int lm  = tid >> 2;         // 0..63
    const int lkq = tid & 3;          // 0..3
    const int lr  = tid >> 4;         // 0..15
    const int lc  = tid & 15;         // 0..15

    // prologue: tile 0
    float4 av = *(const float4*)(X + lm * DM + 4 * lkq);
    float4 bv = *(const float4*)(W + lr * DM + n0 + 4 * lc);
    sA[0][4 * lkq + 0][lm] = av.x;
    sA[0][4 * lkq + 1][lm] = av.y;
    sA[0][4 * lkq + 2][lm] = av.z;
    sA[0][4 * lkq + 3][lm] = av.w;
    *(float4*)(&sB[0][lr][4 * lc]) = bv;
    __syncthreads();

    int p = 0;
#pragma unroll 1
    for (int kt = 0; kt < 16; kt++) {
        float4 av2, bv2;
        if (kt < 15) {
            av2 = *(const float4*)(X + lm * DM + (kt + 1) * 16 + 4 * lkq);
            bv2 = *(const float4*)(W + ((kt + 1) * 16 + lr) * DM + n0 + 4 * lc);
        }
#pragma unroll
        for (int kk = 0; kk < 16; kk++) {
            float4 a = *(const float4*)(&sA[p][kk][ty * 4]);
            float4 b = *(const float4*)(&sB[p][kk][tx * 4]);
            acc[0][0] += a.x * b.x; acc[0][1] += a.x * b.y; acc[0][2] += a.x * b.z; acc[0][3] += a.x * b.w;
            acc[1][0] += a.y * b.x; acc[1][1] += a.y * b.y; acc[1][2] += a.y * b.z; acc[1][3] += a.y * b.w;
            acc[2][0] += a.z * b.x; acc[2][1] += a.z * b.y; acc[2][2] += a.z * b.z; acc[2][3] += a.z * b.w;
            acc[3][0] += a.w * b.x; acc[3][1] += a.w * b.y; acc[3][2] += a.w * b.z; acc[3][3] += a.w * b.w;
        }
        if (kt < 15) {
            sA[p ^ 1][4 * lkq + 0][lm] = av2.x;
            sA[p ^ 1][4 * lkq + 1][lm] = av2.y;
            sA[p ^ 1][4 * lkq + 2][lm] = av2.z;
            sA[p ^ 1][4 * lkq + 3][lm] = av2.w;
            *(float4*)(&sB[p ^ 1][lr][4 * lc]) = bv2;
        }
        __syncthreads();
        p ^= 1;
    }

    // Epilogue: store exp(2*acc)
#pragma unroll
    for (int i = 0; i < 4; i++) {
        float4 o = make_float4(__expf(2.f * acc[i][0]), __expf(2.f * acc[i][1]),
                               __expf(2.f * acc[i][2]), __expf(2.f * acc[i][3]));
        *(float4*)(Y + (ty * 4 + i) * DM + n0 + tx * 4) = o;
    }
}

// ---------------------------------------------------------------------------
// Score kernel, exp-identity + paired reciprocal:
//   tanh(w+u) = 1 - 2/(Ew*Eu + 1);  sum_d v_d is const per (b,t) -> cancels.
//   score'[t,e] = sum_d v'_d / (Ew[e,d]*Eu[t,d] + 1),  v' = -2v.
//   Pairs share one rcp:  v0/d0 + v1/d1 = (v0*d1 + v1*d0) * rcp(d0*d1).
// Per 2 elems: 2 den-fma + 2 mul + 2 fma + 1 MUFU.RCP  (3 fma-pipe/elem).
// Grid: 256 CTAs x 256 threads (~80 regs -> 3 CTAs/SM).
// Warp w -> e-block [w*64,(w+1)*64); lane owns 8 d's; 4 t per Ew-load.
// ---------------------------------------------------------------------------
__global__ void __launch_bounds__(256)
attn_score(const float* __restrict__ Va, float* __restrict__ out_attn) {
    __shared__ __align__(16) float s_eu[TT * DM];          // 4 KB (staging)
    __shared__ __align__(16) float s_v[DM];                // 1 KB (holds -2v)
    __shared__ __align__(16) float s_score[TE][TT];        // 8 KB, e-major

    const int b    = blockIdx.x >> 6;
    const int t0   = (blockIdx.x & 63) * TT;
    const int tid  = threadIdx.x;
    const int warp = tid >> 5;
    const int lane = tid & 31;

    // ---- Phase A: stage Eu rows and v' = -2v ----
    {
        ((float4*)s_eu)[tid] = ((const float4*)(g_Eu + (size_t)(b * TD + t0) * DM))[tid];
        if (tid < 64) {
            float4 v4 = ((const float4*)Va)[tid];
            ((float4*)s_v)[tid] = make_float4(-2.f * v4.x, -2.f * v4.y,
                                              -2.f * v4.z, -2.f * v4.w);
        }
    }
    __syncthreads();

    // ---- Phase B: scores ----
    {
        const int dl = lane * 8;          // d-base for this lane
        const int eb = warp * 64;         // e-block

        // hoist Eu for all 4 t's (32 regs) and v' (8 regs)
        float eu[4][8];
#pragma unroll
        for (int t = 0; t < 4; t++) {
            const float4* up = (const float4*)(s_eu + t * DM + dl);
            *(float4*)(&eu[t][0]) = up[0];
            *(float4*)(&eu[t][4]) = up[1];
        }
        float v[8];
        {
            const float4* vp = (const float4*)(s_v + dl);
            *(float4*)(&v[0]) = vp[0];
            *(float4*)(&v[4]) = vp[1];
        }

        const float* wr = g_Ew + ((size_t)(b * TE) + eb) * DM + dl;
        float cur[8];
        *(float4*)(&cur[0]) = *(const float4*)(wr);
        *(float4*)(&cur[4]) = *(const float4*)(wr + 4);

#pragma unroll 1
        for (int it = 0; it < 64; it++) {
            // prefetch next e-row (pad overread on final iter; values unused)
            wr += DM;
            float nxt[8];
            *(float4*)(&nxt[0]) = *(const float4*)(wr);
            *(float4*)(&nxt[4]) = *(const float4*)(wr + 4);

            float s4[4];
#pragma unroll
            for (int t = 0; t < 4; t++) {
                float a0 = 0.f, a1 = 0.f;
#pragma unroll
                for (int j = 0; j < 8; j += 4) {
                    // pair 0: d j, j+1
                    float d0 = fmaf(cur[j],     eu[t][j],     1.f);
                    float d1 = fmaf(cur[j + 1], eu[t][j + 1], 1.f);
                    float p0 = d0 * d1;
                    float n0 = v[j] * d1;
                    n0 = fmaf(v[j + 1], d0, n0);
                    a0 = fmaf(n0, frcp(p0), a0);
                    // pair 1: d j+2, j+3
                    float d2 = fmaf(cur[j + 2], eu[t][j + 2], 1.f);
                    float d3 = fmaf(cur[j + 3], eu[t][j + 3], 1.f);
                    float p1 = d2 * d3;
                    float n1 = v[j + 2] * d3;
                    n1 = fmaf(v[j + 3], d2, n1);
                    a1 = fmaf(n1, frcp(p1), a1);
                }
                s4[t] = a0 + a1;
            }
            // butterfly over all 32 lanes (d fully reduced)
#pragma unroll
            for (int off = 16; off > 0; off >>= 1) {
                s4[0] += __shfl_xor_sync(0xffffffffu, s4[0], off);
                s4[1] += __shfl_xor_sync(0xffffffffu, s4[1], off);
                s4[2] += __shfl_xor_sync(0xffffffffu, s4[2], off);
                s4[3] += __shfl_xor_sync(0xffffffffu, s4[3], off);
            }
            if (lane == 0)
                *(float4*)(&s_score[eb + it][0]) = make_float4(s4[0], s4[1], s4[2], s4[3]);

#pragma unroll
            for (int j = 0; j < 8; j++) cur[j] = nxt[j];
        }
    }
    __syncthreads();

    // ---- Phase C: softmax over e (warps 0..3, one t each), write attn ----
    if (warp < TT) {
        const int t = warp;
        float vals[16];
        float mx = -1e30f;
#pragma unroll
        for (int k = 0; k < 16; k++) {
            vals[k] = s_score[lane + 32 * k][t];
            mx = fmaxf(mx, vals[k]);
        }
#pragma unroll
        for (int off = 16; off > 0; off >>= 1)
            mx = fmaxf(mx, __shfl_xor_sync(0xffffffffu, mx, off));
        float sum = 0.f;
#pragma unroll
        for (int k = 0; k < 16; k++) {
            vals[k] = exp2f((vals[k] - mx) * 1.4426950408889634f);
            sum += vals[k];
        }
#pragma unroll
        for (int off = 16; off > 0; off >>= 1)
            sum += __shfl_xor_sync(0xffffffffu, sum, off);
        const float inv = 1.0f / sum;
        float* arow = out_attn + ((size_t)(b * TD + t0 + t)) * TE;
#pragma unroll
        for (int k = 0; k < 16; k++)
            arow[lane + 32 * k] = vals[k] * inv;
    }
}

// ---------------------------------------------------------------------------
// Context GEMM: ctx[b,t,d] = sum_e attn[b,t,e] * enc[b,e,d].
// BM=32 (t), BN=64 (d), BK=32 (e). 256 threads, thread = 2m x 4n.
// ---------------------------------------------------------------------------
__global__ void __launch_bounds__(256)
attn_ctx(const float* __restrict__ enc, const float* __restrict__ attn,
         float* __restrict__ out_ctx) {
    __shared__ float sAttT[32][32];   // [e][t] (transposed on store)
    __shared__ float sEnc[32][64];    // [e][d]

    const int b  = blockIdx.z;
    const int t0 = blockIdx.x * 32;
    const int d0 = blockIdx.y * 64;
    const int tid = threadIdx.x;
    const int tx = tid & 15;          // n-sub (4 d's)
    const int ty = tid >> 4;          // m-sub (2 t's)

    const float* attb = attn + ((size_t)(b * TD + t0)) * TE;
    const float* encb = enc + (size_t)b * TE * DM;

    float acc[2][4];
#pragma unroll
    for (int i = 0; i < 2; i++)
#pragma unroll
        for (int j = 0; j < 4; j++) acc[i][j] = 0.f;

    const int am = tid >> 3;          // 0..31 t-row for attn load
    const int ak = (tid & 7) * 4;     // e-chunk
    const int er = tid >> 4;          // 0..15 e-row for enc load
    const int ec = (tid & 15) * 4;    // d-chunk

#pragma unroll 1
    for (int k0 = 0; k0 < TE; k0 += 32) {
        float4 a = *(const float4*)(attb + (size_t)am * TE + k0 + ak);
        float4 e0 = *(const float4*)(encb + (size_t)(k0 + er) * DM + d0 + ec);
        float4 e1 = *(const float4*)(encb + (size_t)(k0 + 16 + er) * DM + d0 + ec);
        sAttT[ak + 0][am] = a.x;
        sAttT[ak + 1][am] = a.y;
        sAttT[ak + 2][am] = a.z;
        sAttT[ak + 3][am] = a.w;
        *(float4*)(&sEnc[er][ec])      = e0;
        *(float4*)(&sEnc[16 + er][ec]) = e1;
        __syncthreads();

#pragma unroll
        for (int k = 0; k < 32; k++) {
            float2 av2 = *(const float2*)(&sAttT[k][ty * 2]);
            float4 bv = *(const float4*)(&sEnc[k][tx * 4]);
            acc[0][0] = fmaf(av2.x, bv.x, acc[0][0]);
            acc[0][1] = fmaf(av2.x, bv.y, acc[0][1]);
            acc[0][2] = fmaf(av2.x, bv.z, acc[0][2]);
            acc[0][3] = fmaf(av2.x, bv.w, acc[0][3]);
            acc[1][0] = fmaf(av2.y, bv.x, acc[1][0]);
            acc[1][1] = fmaf(av2.y, bv.y, acc[1][1]);
            acc[1][2] = fmaf(av2.y, bv.z, acc[1][2]);
            acc[1][3] = fmaf(av2.y, bv.w, acc[1][3]);
        }
        __syncthreads();
    }

#pragma unroll
    for (int i = 0; i < 2; i++) {
        float4 o = make_float4(acc[i][0], acc[i][1], acc[i][2], acc[i][3]);
        *(float4*)(out_ctx + ((size_t)(b * TD + t0 + ty * 2 + i)) * DM + d0 + tx * 4) = o;
    }
}

extern "C" void kernel_launch(void* const* d_in, const int* in_sizes, int n_in,
                              void* d_out, int out_size) {
    const float* enc = (const float*)d_in[0];   // [4,512,256]
    const float* dec = (const float*)d_in[1];   // [4,256,256]
    const float* Wa  = (const float*)d_in[2];   // [256,256]
    const float* Ua  = (const float*)d_in[3];   // [256,256]
    const float* Va  = (const float*)d_in[4];   // [256,1]

    float* out      = (float*)d_out;
    float* out_ctx  = out;                          // [4,256,256]
    float* out_attn = out + (size_t)BB * TD * DM;   // [4,256,512]

    // Projections + exp epilogue: 192 CTAs (measured-best shape)
    proj_gemm2<<<dim3((BB * TE + BB * TD) / 64, DM / 64), 256>>>(enc, dec, Wa, Ua);

    // Scores + softmax: 256 CTAs x 256 threads
    attn_score<<<BB * (TD / TT), 256>>>(Va, out_attn);

    // Context GEMM: 128 CTAs
    attn_ctx<<<dim3(TD / 32, DM / 64, BB), 256>>>(enc, out_attn, out_ctx);
}

// round 13
// speedup vs baseline: 1.3699x; 1.0197x over previous
#include <cuda_runtime.h>
#include <cuda_bf16.h>
#include <cuda_fp16.h>
#include <math.h>

// Problem dims (fixed by reference setup_inputs)
#define BB 4
#define TE 512
#define TD 256
#define DM 256
#define TT 4   // t-rows per CTA in score kernel

// Scratch (allocation-free __device__ globals). Pads cover prefetch overread.
__device__ __align__(16) __half g_EwH[BB * TE * DM + 2 * DM]; // exp(2*enc@W_a), f16
__device__ __align__(16) float  g_Eu[BB * TD * DM];           // exp(2*dec@U_a), f32

__device__ __forceinline__ float frcp(float x) {
    float y; asm("rcp.approx.ftz.f32 %0, %1;" : "=f"(y) : "f"(x)); return y;
}

// ---------------------------------------------------------------------------
// Combined projection GEMM (enc@W_a and dec@U_a in one launch).
// BM=64, BN=64, BK=16, 256 threads, 4x4/thread, double-buffered.
// Rows 0..2047 -> g_EwH (exp(2x) in HALF), 2048..3071 -> g_Eu (exp(2x) f32).
// Half scratch stores measured ~9us faster than f32 (R2-R6 vs R7-R12).
// ---------------------------------------------------------------------------
__global__ void __launch_bounds__(256)
proj_gemm2(const float* __restrict__ enc, const float* __restrict__ dec,
           const float* __restrict__ Wa,  const float* __restrict__ Ua) {
    __shared__ float sA[2][16][64];   // sA[p][k][m]
    __shared__ float sB[2][16][64];   // sB[p][k][n]

    const int tid = threadIdx.x;
    const int tx = tid & 15;          // n-sub
    const int ty = tid >> 4;          // m-sub
    const int row0 = blockIdx.x * 64;
    const int n0   = blockIdx.y * 64;

    const bool isW = (row0 < BB * TE);
    const float* X;
    const float* W;
    if (isW) { X = enc + (size_t)row0 * DM;              W = Wa; }
    else     { X = dec + (size_t)(row0 - BB * TE) * DM;  W = Ua; }

    float acc[4][4];
#pragma unroll
    for (int i = 0; i < 4; i++)
#pragma unroll
        for (int j = 0; j < 4; j++) acc[i][j] = 0.f;

    const int lm  = tid >> 2;         // 0..63
    const int lkq = tid & 3;          // 0..3
    const int lr  = tid >> 4;         // 0..15
    const int lc  = tid & 15;         // 0..15

    // prologue: tile 0
    float4 av = *(const float4*)(X + lm * DM + 4 * lkq);
    float4 bv = *(const float4*)(W + lr * DM + n0 + 4 * lc);
    sA[0][4 * lkq + 0][lm] = av.x;
    sA[0][4 * lkq + 1][lm] = av.y;
    sA[0][4 * lkq + 2][lm] = av.z;
    sA[0][4 * lkq + 3][lm] = av.w;
    *(float4*)(&sB[0][lr][4 * lc]) = bv;
    __syncthreads();

    int p = 0;
#pragma unroll 1
    for (int kt = 0; kt < 16; kt++) {
        float4 av2, bv2;
        if (kt < 15) {
            av2 = *(const float4*)(X + lm * DM + (kt + 1) * 16 + 4 * lkq);
            bv2 = *(const float4*)(W + ((kt + 1) * 16 + lr) * DM + n0 + 4 * lc);
        }
#pragma unroll
        for (int kk = 0; kk < 16; kk++) {
            float4 a = *(const float4*)(&sA[p][kk][ty * 4]);
            float4 b = *(const float4*)(&sB[p][kk][tx * 4]);
            acc[0][0] += a.x * b.x; acc[0][1] += a.x * b.y; acc[0][2] += a.x * b.z; acc[0][3] += a.x * b.w;
            acc[1][0] += a.y * b.x; acc[1][1] += a.y * b.y; acc[1][2] += a.y * b.z; acc[1][3] += a.y * b.w;
            acc[2][0] += a.z * b.x; acc[2][1] += a.z * b.y; acc[2][2] += a.z * b.z; acc[2][3] += a.z * b.w;
            acc[3][0] += a.w * b.x; acc[3][1] += a.w * b.y; acc[3][2] += a.w * b.z; acc[3][3] += a.w * b.w;
        }
        if (kt < 15) {
            sA[p ^ 1][4 * lkq + 0][lm] = av2.x;
            sA[p ^ 1][4 * lkq + 1][lm] = av2.y;
            sA[p ^ 1][4 * lkq + 2][lm] = av2.z;
            sA[p ^ 1][4 * lkq + 3][lm] = av2.w;
            *(float4*)(&sB[p ^ 1][lr][4 * lc]) = bv2;
        }
        __syncthreads();
        p ^= 1;
    }

    // Epilogue: exp(2*acc). Ew -> half, Eu -> f32.
    if (isW) {
        __half* Y = g_EwH + (size_t)row0 * DM;
#pragma unroll
        for (int i = 0; i < 4; i++) {
            __half2 p0 = __floats2half2_rn(__expf(2.f * acc[i][0]),
                                           __expf(2.f * acc[i][1]));
            __half2 p1 = __floats2half2_rn(__expf(2.f * acc[i][2]),
                                           __expf(2.f * acc[i][3]));
            uint2 o;
            o.x = *reinterpret_cast<unsigned*>(&p0);
            o.y = *reinterpret_cast<unsigned*>(&p1);
            *(uint2*)(Y + (ty * 4 + i) * DM + n0 + tx * 4) = o;
        }
    } else {
        float* Y = g_Eu + (size_t)(row0 - BB * TE) * DM;
#pragma unroll
        for (int i = 0; i < 4; i++) {
            float4 o = make_float4(__expf(2.f * acc[i][0]), __expf(2.f * acc[i][1]),
                                   __expf(2.f * acc[i][2]), __expf(2.f * acc[i][3]));
            *(float4*)(Y + (ty * 4 + i) * DM + n0 + tx * 4) = o;
        }
    }
}

// ---------------------------------------------------------------------------
// Score kernel, exp-identity + paired reciprocal, HALF Ew stream:
//   tanh(w+u) = 1 - 2/(Ew*Eu + 1);  sum_d v_d is const per (b,t) -> cancels.
//   score'[t,e] = sum_d v'_d / (Ew[e,d]*Eu[t,d] + 1),  v' = -2v.
//   Pairs share one rcp:  v0/d0 + v1/d1 = (v0*d1 + v1*d0) * rcp(d0*d1).
// Lane owns 8 d's = 16 B of half Ew = ONE LDG.128 per e-row (was two f32).
// F2F converts ride the idle ALU pipe. Math stays f32 (only Ew quantized).
// Grid: 256 CTAs x 256 threads. Warp w -> e-block [w*64,(w+1)*64).
// ---------------------------------------------------------------------------
__global__ void __launch_bounds__(256)
attn_score(const float* __restrict__ Va, float* __restrict__ out_attn) {
    __shared__ __align__(16) float s_eu[TT * DM];          // 4 KB (staging)
    __shared__ __align__(16) float s_v[DM];                // 1 KB (holds -2v)
    __shared__ __align__(16) float s_score[TE][TT];        // 8 KB, e-major

    const int b    = blockIdx.x >> 6;
    const int t0   = (blockIdx.x & 63) * TT;
    const int tid  = threadIdx.x;
    const int warp = tid >> 5;
    const int lane = tid & 31;

    // ---- Phase A: stage Eu rows and v' = -2v ----
    {
        ((float4*)s_eu)[tid] = ((const float4*)(g_Eu + (size_t)(b * TD + t0) * DM))[tid];
        if (tid < 64) {
            float4 v4 = ((const float4*)Va)[tid];
            ((float4*)s_v)[tid] = make_float4(-2.f * v4.x, -2.f * v4.y,
                                              -2.f * v4.z, -2.f * v4.w);
        }
    }
    __syncthreads();

    // ---- Phase B: scores ----
    {
        const int dl = lane * 8;          // d-base for this lane
        const int eb = warp * 64;         // e-block

        // hoist Eu for all 4 t's (32 regs) and v' (8 regs)
        float eu[4][8];
#pragma unroll
        for (int t = 0; t < 4; t++) {
            const float4* up = (const float4*)(s_eu + t * DM + dl);
            *(float4*)(&eu[t][0]) = up[0];
            *(float4*)(&eu[t][4]) = up[1];
        }
        float v[8];
        {
            const float4* vp = (const float4*)(s_v + dl);
            *(float4*)(&v[0]) = vp[0];
            *(float4*)(&v[4]) = vp[1];
        }

        const uint4* wr = (const uint4*)(g_EwH + ((size_t)(b * TE) + eb) * DM + dl);
        uint4 cur = *wr;

#pragma unroll 1
        for (int it = 0; it < 64; it++) {
            // prefetch next e-row (pad overread on final iter; values unused)
            wr += DM / 8;                 // one e-row = 256 halves = 32 uint4... (DM/8 uint4)
            uint4 nxt = *wr;

            // convert 8 halves -> 8 floats (ALU pipe)
            float w8[8];
            {
                const __half2* h = (const __half2*)&cur;
#pragma unroll
                for (int q = 0; q < 4; q++) {
                    float2 f = __half22float2(h[q]);
                    w8[2 * q]     = f.x;
                    w8[2 * q + 1] = f.y;
                }
            }

            float s4[4];
#pragma unroll
            for (int t = 0; t < 4; t++) {
                float a0 = 0.f, a1 = 0.f;
#pragma unroll
                for (int j = 0; j < 8; j += 4) {
                    // pair 0: d j, j+1
                    float d0 = fmaf(w8[j],     eu[t][j],     1.f);
                    float d1 = fmaf(w8[j + 1], eu[t][j + 1], 1.f);
                    float p0 = d0 * d1;
                    float n0 = v[j] * d1;
                    n0 = fmaf(v[j + 1], d0, n0);
                    a0 = fmaf(n0, frcp(p0), a0);
                    // pair 1: d j+2, j+3
                    float d2 = fmaf(w8[j + 2], eu[t][j + 2], 1.f);
                    float d3 = fmaf(w8[j + 3], eu[t][j + 3], 1.f);
                    float p1 = d2 * d3;
                    float n1 = v[j + 2] * d3;
                    n1 = fmaf(v[j + 3], d2, n1);
                    a1 = fmaf(n1, frcp(p1), a1);
                }
                s4[t] = a0 + a1;
            }
            // butterfly over all 32 lanes (d fully reduced)
#pragma unroll
            for (int off = 16; off > 0; off >>= 1) {
                s4[0] += __shfl_xor_sync(0xffffffffu, s4[0], off);
                s4[1] += __shfl_xor_sync(0xffffffffu, s4[1], off);
                s4[2] += __shfl_xor_sync(0xffffffffu, s4[2], off);
                s4[3] += __shfl_xor_sync(0xffffffffu, s4[3], off);
            }
            if (lane == 0)
                *(float4*)(&s_score[eb + it][0]) = make_float4(s4[0], s4[1], s4[2], s4[3]);

            cur = nxt;
        }
    }
    __syncthreads();

    // ---- Phase C: softmax over e (warps 0..3, one t each), write attn ----
    if (warp < TT) {
        const int t = warp;
        float vals[16];
        float mx = -1e30f;
#pragma unroll
        for (int k = 0; k < 16; k++) {
            vals[k] = s_score[lane + 32 * k][t];
            mx = fmaxf(mx, vals[k]);
        }
#pragma unroll
        for (int off = 16; off > 0; off >>= 1)
            mx = fmaxf(mx, __shfl_xor_sync(0xffffffffu, mx, off));
        float sum = 0.f;
#pragma unroll
        for (int k = 0; k < 16; k++) {
            vals[k] = exp2f((vals[k] - mx) * 1.4426950408889634f);
            sum += vals[k];
        }
#pragma unroll
        for (int off = 16; off > 0; off >>= 1)
            sum += __shfl_xor_sync(0xffffffffu, sum, off);
        const float inv = 1.0f / sum;
        float* arow = out_attn + ((size_t)(b * TD + t0 + t)) * TE;
#pragma unroll
        for (int k = 0; k < 16; k++)
            arow[lane + 32 * k] = vals[k] * inv;
    }
}

// ---------------------------------------------------------------------------
// Context GEMM: ctx[b,t,d] = sum_e attn[b,t,e] * enc[b,e,d].
// BM=32 (t), BN=64 (d), BK=32 (e). 256 threads, thread = 2m x 4n.
// ---------------------------------------------------------------------------
__global__ void __launch_bounds__(256)
attn_ctx(const float* __restrict__ enc, const float* __restrict__ attn,
         float* __restrict__ out_ctx) {
    __shared__ float sAttT[32][32];   // [e][t] (transposed on store)
    __shared__ float sEnc[32][64];    // [e][d]

    const int b  = blockIdx.z;
    const int t0 = blockIdx.x * 32;
    const int d0 = blockIdx.y * 64;
    const int tid = threadIdx.x;
    const int tx = tid & 15;          // n-sub (4 d's)
    const int ty = tid >> 4;          // m-sub (2 t's)

    const float* attb = attn + ((size_t)(b * TD + t0)) * TE;
    const float* encb = enc + (size_t)b * TE * DM;

    float acc[2][4];
#pragma unroll
    for (int i = 0; i < 2; i++)
#pragma unroll
        for (int j = 0; j < 4; j++) acc[i][j] = 0.f;

    const int am = tid >> 3;          // 0..31 t-row for attn load
    const int ak = (tid & 7) * 4;     // e-chunk
    const int er = tid >> 4;          // 0..15 e-row for enc load
    const int ec = (tid & 15) * 4;    // d-chunk

#pragma unroll 1
    for (int k0 = 0; k0 < TE; k0 += 32) {
        float4 a = *(const float4*)(attb + (size_t)am * TE + k0 + ak);
        float4 e0 = *(const float4*)(encb + (size_t)(k0 + er) * DM + d0 + ec);
        float4 e1 = *(const float4*)(encb + (size_t)(k0 + 16 + er) * DM + d0 + ec);
        sAttT[ak + 0][am] = a.x;
        sAttT[ak + 1][am] = a.y;
        sAttT[ak + 2][am] = a.z;
        sAttT[ak + 3][am] = a.w;
        *(float4*)(&sEnc[er][ec])      = e0;
        *(float4*)(&sEnc[16 + er][ec]) = e1;
        __syncthreads();

#pragma unroll
        for (int k = 0; k < 32; k++) {
            float2 av2 = *(const float2*)(&sAttT[k][ty * 2]);
            float4 bv = *(const float4*)(&sEnc[k][tx * 4]);
            acc[0][0] = fmaf(av2.x, bv.x, acc[0][0]);
            acc[0][1] = fmaf(av2.x, bv.y, acc[0][1]);
            acc[0][2] = fmaf(av2.x, bv.z, acc[0][2]);
            acc[0][3] = fmaf(av2.x, bv.w, acc[0][3]);
            acc[1][0] = fmaf(av2.y, bv.x, acc[1][0]);
            acc[1][1] = fmaf(av2.y, bv.y, acc[1][1]);
            acc[1][2] = fmaf(av2.y, bv.z, acc[1][2]);
            acc[1][3] = fmaf(av2.y, bv.w, acc[1][3]);
        }
        __syncthreads();
    }

#pragma unroll
    for (int i = 0; i < 2; i++) {
        float4 o = make_float4(acc[i][0], acc[i][1], acc[i][2], acc[i][3]);
        *(float4*)(out_ctx + ((size_t)(b * TD + t0 + ty * 2 + i)) * DM + d0 + tx * 4) = o;
    }
}

extern "C" void kernel_launch(void* const* d_in, const int* in_sizes, int n_in,
                              void* d_out, int out_size) {
    const float* enc = (const float*)d_in[0];   // [4,512,256]
    const float* dec = (const float*)d_in[1];   // [4,256,256]
    const float* Wa  = (const float*)d_in[2];   // [256,256]
    const float* Ua  = (const float*)d_in[3];   // [256,256]
    const float* Va  = (const float*)d_in[4];   // [256,1]

    float* out      = (float*)d_out;
    float* out_ctx  = out;                          // [4,256,256]
    float* out_attn = out + (size_t)BB * TD * DM;   // [4,256,512]

    // Projections + exp epilogue (Ew half, Eu f32): 192 CTAs
    proj_gemm2<<<dim3((BB * TE + BB * TD) / 64, DM / 64), 256>>>(enc, dec, Wa, Ua);

    // Scores + softmax: 256 CTAs x 256 threads
    attn_score<<<BB * (TD / TT), 256>>>(Va, out_attn);

    // Context GEMM: 128 CTAs
    attn_ctx<<<dim3(TD / 32, DM / 64, BB), 256>>>(enc, out_attn, out_ctx);
}

// round 14
// speedup vs baseline: 1.4882x; 1.0864x over previous
#include <cuda_runtime.h>
#include <cuda_bf16.h>
#include <cuda_fp16.h>
#include <math.h>

// Problem dims (fixed by reference setup_inputs)
#define BB 4
#define TE 512
#define TD 256
#define DM 256
#define TT 4   // t-rows per CTA in score kernel

// Scratch (allocation-free __device__ globals). Pads cover prefetch overread.
__device__ __align__(16) __half g_EwH[BB * TE * DM + 2 * DM]; // exp(2*enc@W_a), f16
__device__ __align__(16) float  g_Eu[BB * TD * DM];           // exp(2*dec@U_a), f32

__device__ __forceinline__ float frcp(float x) {
    float y; asm("rcp.approx.ftz.f32 %0, %1;" : "=f"(y) : "f"(x)); return y;
}

// ---------------------------------------------------------------------------
// Combined projection GEMM (enc@W_a and dec@U_a in one launch).
// BM=64, BN=64, BK=16, 256 threads, 4x4/thread, double-buffered.
// Rows 0..2047 -> g_EwH (exp(2x) in HALF), 2048..3071 -> g_Eu (exp(2x) f32).
// ---------------------------------------------------------------------------
__global__ void __launch_bounds__(256)
proj_gemm2(const float* __restrict__ enc, const float* __restrict__ dec,
           const float* __restrict__ Wa,  const float* __restrict__ Ua) {
    __shared__ float sA[2][16][64];   // sA[p][k][m]
    __shared__ float sB[2][16][64];   // sB[p][k][n]

    const int tid = threadIdx.x;
    const int tx = tid & 15;          // n-sub
    const int ty = tid >> 4;          // m-sub
    const int row0 = blockIdx.x * 64;
    const int n0   = blockIdx.y * 64;

    const bool isW = (row0 < BB * TE);
    const float* X;
    const float* W;
    if (isW) { X = enc + (size_t)row0 * DM;              W = Wa; }
    else     { X = dec + (size_t)(row0 - BB * TE) * DM;  W = Ua; }

    float acc[4][4];
#pragma unroll
    for (int i = 0; i < 4; i++)
#pragma unroll
        for (int j = 0; j < 4; j++) acc[i][j] = 0.f;

    const int lm  = tid >> 2;         // 0..63
    const int lkq = tid & 3;          // 0..3
    const int lr  = tid >> 4;         // 0..15
    const int lc  = tid & 15;         // 0..15

    // prologue: tile 0
    float4 av = *(const float4*)(X + lm * DM + 4 * lkq);
    float4 bv = *(const float4*)(W + lr * DM + n0 + 4 * lc);
    sA[0][4 * lkq + 0][lm] = av.x;
    sA[0][4 * lkq + 1][lm] = av.y;
    sA[0][4 * lkq + 2][lm] = av.z;
    sA[0][4 * lkq + 3][lm] = av.w;
    *(float4*)(&sB[0][lr][4 * lc]) = bv;
    __syncthreads();

    int p = 0;
#pragma unroll 1
    for (int kt = 0; kt < 16; kt++) {
        float4 av2, bv2;
        if (kt < 15) {
            av2 = *(const float4*)(X + lm * DM + (kt + 1) * 16 + 4 * lkq);
            bv2 = *(const float4*)(W + ((kt + 1) * 16 + lr) * DM + n0 + 4 * lc);
        }
#pragma unroll
        for (int kk = 0; kk < 16; kk++) {
            float4 a = *(const float4*)(&sA[p][kk][ty * 4]);
            float4 b = *(const float4*)(&sB[p][kk][tx * 4]);
            acc[0][0] += a.x * b.x; acc[0][1] += a.x * b.y; acc[0][2] += a.x * b.z; acc[0][3] += a.x * b.w;
            acc[1][0] += a.y * b.x; acc[1][1] += a.y * b.y; acc[1][2] += a.y * b.z; acc[1][3] += a.y * b.w;
            acc[2][0] += a.z * b.x; acc[2][1] += a.z * b.y; acc[2][2] += a.z * b.z; acc[2][3] += a.z * b.w;
            acc[3][0] += a.w * b.x; acc[3][1] += a.w * b.y; acc[3][2] += a.w * b.z; acc[3][3] += a.w * b.w;
        }
        if (kt < 15) {
            sA[p ^ 1][4 * lkq + 0][lm] = av2.x;
            sA[p ^ 1][4 * lkq + 1][lm] = av2.y;
            sA[p ^ 1][4 * lkq + 2][lm] = av2.z;
            sA[p ^ 1][4 * lkq + 3][lm] = av2.w;
            *(float4*)(&sB[p ^ 1][lr][4 * lc]) = bv2;
        }
        __syncthreads();
        p ^= 1;
    }

    // Epilogue: exp(2*acc). Ew -> half, Eu -> f32.
    if (isW) {
        __half* Y = g_EwH + (size_t)row0 * DM;
#pragma unroll
        for (int i = 0; i < 4; i++) {
            __half2 p0 = __floats2half2_rn(__expf(2.f * acc[i][0]),
                                           __expf(2.f * acc[i][1]));
            __half2 p1 = __floats2half2_rn(__expf(2.f * acc[i][2]),
                                           __expf(2.f * acc[i][3]));
            uint2 o;
            o.x = *reinterpret_cast<unsigned*>(&p0);
            o.y = *reinterpret_cast<unsigned*>(&p1);
            *(uint2*)(Y + (ty * 4 + i) * DM + n0 + tx * 4) = o;
        }
    } else {
        float* Y = g_Eu + (size_t)(row0 - BB * TE) * DM;
#pragma unroll
        for (int i = 0; i < 4; i++) {
            float4 o = make_float4(__expf(2.f * acc[i][0]), __expf(2.f * acc[i][1]),
                                   __expf(2.f * acc[i][2]), __expf(2.f * acc[i][3]));
            *(float4*)(Y + (ty * 4 + i) * DM + n0 + tx * 4) = o;
        }
    }
}

// ---------------------------------------------------------------------------
// FUSED kernel: score (exp-identity + paired rcp) -> softmax -> context.
//   tanh(w+u) = 1 - 2/(Ew*Eu + 1);  sum_d v_d is const per (b,t) -> cancels.
//   score'[t,e] = sum_d v'_d / (Ew[e,d]*Eu[t,d] + 1),  v' = -2v.
//   Pairs share one rcp:  v0/d0 + v1/d1 = (v0*d1 + v1*d0) * rcp(d0*d1).
// Grid: 256 CTAs x 256 threads. Warp w -> e-block [w*64,(w+1)*64); lane owns
// 8 d's (ONE LDG.128 of half Ew per e-row); 4 t per Ew-load.
// Phase D (context) fused: s_score holds attn weights after Phase C.
// ---------------------------------------------------------------------------
__global__ void __launch_bounds__(256)
attn_score(const float* __restrict__ enc, const float* __restrict__ Va,
           float* __restrict__ out_ctx, float* __restrict__ out_attn) {
    __shared__ __align__(16) float s_eu[TT * DM];          // 4 KB (staging)
    __shared__ __align__(16) float s_v[DM];                // 1 KB (holds -2v)
    __shared__ __align__(16) float s_score[TE][TT];        // 8 KB, e-major

    const int b    = blockIdx.x >> 6;
    const int t0   = (blockIdx.x & 63) * TT;
    const int tid  = threadIdx.x;
    const int warp = tid >> 5;
    const int lane = tid & 31;

    // ---- Phase A: stage Eu rows and v' = -2v ----
    {
        ((float4*)s_eu)[tid] = ((const float4*)(g_Eu + (size_t)(b * TD + t0) * DM))[tid];
        if (tid < 64) {
            float4 v4 = ((const float4*)Va)[tid];
            ((float4*)s_v)[tid] = make_float4(-2.f * v4.x, -2.f * v4.y,
                                              -2.f * v4.z, -2.f * v4.w);
        }
    }
    __syncthreads();

    // ---- Phase B: scores ----
    {
        const int dl = lane * 8;          // d-base for this lane
        const int eb = warp * 64;         // e-block

        // hoist Eu for all 4 t's (32 regs) and v' (8 regs)
        float eu[4][8];
#pragma unroll
        for (int t = 0; t < 4; t++) {
            const float4* up = (const float4*)(s_eu + t * DM + dl);
            *(float4*)(&eu[t][0]) = up[0];
            *(float4*)(&eu[t][4]) = up[1];
        }
        float v[8];
        {
            const float4* vp = (const float4*)(s_v + dl);
            *(float4*)(&v[0]) = vp[0];
            *(float4*)(&v[4]) = vp[1];
        }

        const uint4* wr = (const uint4*)(g_EwH + ((size_t)(b * TE) + eb) * DM + dl);
        uint4 cur = *wr;

#pragma unroll 1
        for (int it = 0; it < 64; it++) {
            // prefetch next e-row (pad overread on final iter; values unused)
            wr += DM / 8;
            uint4 nxt = *wr;

            // convert 8 halves -> 8 floats
            float w8[8];
            {
                const __half2* h = (const __half2*)&cur;
#pragma unroll
                for (int q = 0; q < 4; q++) {
                    float2 f = __half22float2(h[q]);
                    w8[2 * q]     = f.x;
                    w8[2 * q + 1] = f.y;
                }
            }

            float s4[4];
#pragma unroll
            for (int t = 0; t < 4; t++) {
                float a0 = 0.f, a1 = 0.f;
#pragma unroll
                for (int j = 0; j < 8; j += 4) {
                    // pair 0: d j, j+1
                    float d0 = fmaf(w8[j],     eu[t][j],     1.f);
                    float d1 = fmaf(w8[j + 1], eu[t][j + 1], 1.f);
                    float p0 = d0 * d1;
                    float n0 = v[j] * d1;
                    n0 = fmaf(v[j + 1], d0, n0);
                    a0 = fmaf(n0, frcp(p0), a0);
                    // pair 1: d j+2, j+3
                    float d2 = fmaf(w8[j + 2], eu[t][j + 2], 1.f);
                    float d3 = fmaf(w8[j + 3], eu[t][j + 3], 1.f);
                    float p1 = d2 * d3;
                    float n1 = v[j + 2] * d3;
                    n1 = fmaf(v[j + 3], d2, n1);
                    a1 = fmaf(n1, frcp(p1), a1);
                }
                s4[t] = a0 + a1;
            }
            // butterfly over all 32 lanes (d fully reduced)
#pragma unroll
            for (int off = 16; off > 0; off >>= 1) {
                s4[0] += __shfl_xor_sync(0xffffffffu, s4[0], off);
                s4[1] += __shfl_xor_sync(0xffffffffu, s4[1], off);
                s4[2] += __shfl_xor_sync(0xffffffffu, s4[2], off);
                s4[3] += __shfl_xor_sync(0xffffffffu, s4[3], off);
            }
            if (lane == 0)
                *(float4*)(&s_score[eb + it][0]) = make_float4(s4[0], s4[1], s4[2], s4[3]);

            cur = nxt;
        }
    }
    __syncthreads();

    // ---- Phase C: softmax over e (warps 0..3, one t each) ----
    // Writes attn weights to gmem AND back into s_score for fused Phase D.
    if (warp < TT) {
        const int t = warp;
        float vals[16];
        float mx = -1e30f;
#pragma unroll
        for (int k = 0; k < 16; k++) {
            vals[k] = s_score[lane + 32 * k][t];
            mx = fmaxf(mx, vals[k]);
        }
#pragma unroll
        for (int off = 16; off > 0; off >>= 1)
            mx = fmaxf(mx, __shfl_xor_sync(0xffffffffu, mx, off));
        float sum = 0.f;
#pragma unroll
        for (int k = 0; k < 16; k++) {
            vals[k] = exp2f((vals[k] - mx) * 1.4426950408889634f);
            sum += vals[k];
        }
#pragma unroll
        for (int off = 16; off > 0; off >>= 1)
            sum += __shfl_xor_sync(0xffffffffu, sum, off);
        const float inv = 1.0f / sum;
        float* arow = out_attn + ((size_t)(b * TD + t0 + t)) * TE;
#pragma unroll
        for (int k = 0; k < 16; k++) {
            const float w = vals[k] * inv;
            s_score[lane + 32 * k][t] = w;
            arow[lane + 32 * k] = w;
        }
    }
    __syncthreads();

    // ---- Phase D: context = attn @ enc. Thread owns d = tid. ----
    {
        const int d = tid;
        const float* encp = enc + (size_t)b * TE * DM + d;
        float a0 = 0.f, a1 = 0.f, a2 = 0.f, a3 = 0.f;
#pragma unroll 8
        for (int e = 0; e < TE; e++) {
            const float ev = __ldg(encp + (size_t)e * DM);
            float4 aw = *(const float4*)(&s_score[e][0]);
            a0 = fmaf(aw.x, ev, a0);
            a1 = fmaf(aw.y, ev, a1);
            a2 = fmaf(aw.z, ev, a2);
            a3 = fmaf(aw.w, ev, a3);
        }
        out_ctx[((size_t)(b * TD + t0 + 0)) * DM + d] = a0;
        out_ctx[((size_t)(b * TD + t0 + 1)) * DM + d] = a1;
        out_ctx[((size_t)(b * TD + t0 + 2)) * DM + d] = a2;
        out_ctx[((size_t)(b * TD + t0 + 3)) * DM + d] = a3;
    }
}

extern "C" void kernel_launch(void* const* d_in, const int* in_sizes, int n_in,
                              void* d_out, int out_size) {
    const float* enc = (const float*)d_in[0];   // [4,512,256]
    const float* dec = (const float*)d_in[1];   // [4,256,256]
    const float* Wa  = (const float*)d_in[2];   // [256,256]
    const float* Ua  = (const float*)d_in[3];   // [256,256]
    const float* Va  = (const float*)d_in[4];   // [256,1]

    float* out      = (float*)d_out;
    float* out_ctx  = out;                          // [4,256,256]
    float* out_attn = out + (size_t)BB * TD * DM;   // [4,256,512]

    // Projections + exp epilogue (Ew half, Eu f32): 192 CTAs
    proj_gemm2<<<dim3((BB * TE + BB * TD) / 64, DM / 64), 256>>>(enc, dec, Wa, Ua);

    // Fused scores + softmax + context: 256 CTAs x 256 threads
    attn_score<<<BB * (TD / TT), 256>>>(enc, Va, out_ctx, out_attn);
}